// round 3
// baseline (speedup 1.0000x reference)
#include <cuda_runtime.h>
#include <math_constants.h>
#include <cstdint>

// Problem constants
#define EMBED_D   128
#define N_EMBED   10000
#define N_PAD     10048          // padded to multiple of BN
#define NSAMP     16384          // 8*64*32
#define BM        128            // samples per block
#define BN        64             // codes per tile
#define NT        (N_PAD / BN)   // 157 code tiles
#define NTHREADS  256

// Scratch (no cudaMalloc allowed)
__device__ float g_cnorm[N_PAD];
__device__ int   g_argmin[NSAMP];
__device__ float g_partial[NSAMP];

// ---------- packed f32x2 helpers (ptxas never auto-fuses FFMA2) ----------
__device__ __forceinline__ void fma2(unsigned long long& d,
                                     unsigned long long a,
                                     unsigned long long b) {
    asm("fma.rn.f32x2 %0, %1, %2, %0;" : "+l"(d) : "l"(a), "l"(b));
}
__device__ __forceinline__ unsigned long long splat2(float v) {
    unsigned long long r;
    asm("mov.b64 %0, {%1, %1};" : "=l"(r) : "f"(v));
    return r;
}
__device__ __forceinline__ void unpack2(unsigned long long p, float& lo, float& hi) {
    asm("mov.b64 {%0, %1}, %2;" : "=f"(lo), "=f"(hi) : "l"(p));
}

// ---------- Kernel A: code norms (||c_j||^2), +INF for pad ----------
__global__ void cnorm_kernel(const float* __restrict__ cm) {
    int j = blockIdx.x * blockDim.x + threadIdx.x;
    if (j >= N_PAD) return;
    if (j >= N_EMBED) { g_cnorm[j] = CUDART_INF_F; return; }
    float s = 0.f;
#pragma unroll 8
    for (int d = 0; d < EMBED_D; d++) {
        float v = cm[(size_t)d * N_EMBED + j];
        s = fmaf(v, v, s);
    }
    g_cnorm[j] = s;
}

// ---------- Kernel B: argmin over codes via tiled fp32x2 GEMM ----------
// score(m,j) = ||c_j||^2 - 2 * <x_m, c_j>   (||x||^2 constant per row -> irrelevant)
extern __shared__ float smem_b[];

__global__ __launch_bounds__(NTHREADS, 1)
void argmin_kernel(const float* __restrict__ X,   // [NSAMP, 128] row-major
                   const float* __restrict__ CM)  // [128, N_EMBED] row-major
{
    float* Xs = smem_b;                 // [128][BM]  (k-major, transposed) 64KB
    float* Cs = smem_b + EMBED_D * BM;  // [128][BN]                        32KB

    const int tid = threadIdx.x;
    const int tx  = tid & 15;   // n-direction (16)
    const int ty  = tid >> 4;   // m-direction (16)
    const int m0  = ty * 8;     // 8 sample rows per thread
    const int nc0 = tx * 4;     // 4 code cols per thread

    // Load X tile [BM][128] -> transposed smem Xs[k][m], float4 per thread
    {
        const float4* Xg = (const float4*)(X + (size_t)blockIdx.x * BM * EMBED_D);
        for (int t = tid; t < BM * EMBED_D / 4; t += NTHREADS) {
            int m = t >> 5;        // 32 float4 per row
            int f = t & 31;
            float4 v = Xg[t];
            int d = f * 4;
            Xs[(d + 0) * BM + m] = v.x;
            Xs[(d + 1) * BM + m] = v.y;
            Xs[(d + 2) * BM + m] = v.z;
            Xs[(d + 3) * BM + m] = v.w;
        }
    }

    float rmin[8];
    int   ridx[8];
#pragma unroll
    for (int i = 0; i < 8; i++) { rmin[i] = CUDART_INF_F; ridx[i] = 0; }

    for (int nt = 0; nt < NT; nt++) {
        const int n0 = nt * BN;

        __syncthreads();  // previous tile's compute done before overwriting Cs
        // Load C tile [128][BN]; OOB columns -> 0 (their cnorm is +INF)
        for (int t = tid; t < EMBED_D * BN / 4; t += NTHREADS) {
            int d = t >> 4;    // 16 float4 per row
            int f = t & 15;
            int n = n0 + f * 4;
            float4 v;
            if (n < N_EMBED)   // N_EMBED % 4 == 0 -> float4 fully valid or fully OOB
                v = *(const float4*)(CM + (size_t)d * N_EMBED + n);
            else
                v = make_float4(0.f, 0.f, 0.f, 0.f);
            *(float4*)&Cs[d * BN + f * 4] = v;
        }
        __syncthreads();

        // acc[i2][j]: packed pair over (m0+2*i2, m0+2*i2+1) x code (nc0+j)
        unsigned long long acc[4][4];
#pragma unroll
        for (int i = 0; i < 4; i++)
#pragma unroll
            for (int j = 0; j < 4; j++) acc[i][j] = 0ull;

#pragma unroll 4
        for (int k = 0; k < EMBED_D; k++) {
            const float* xr = &Xs[k * BM + m0];
            unsigned long long a0 = *(const unsigned long long*)(xr + 0);
            unsigned long long a1 = *(const unsigned long long*)(xr + 2);
            unsigned long long a2 = *(const unsigned long long*)(xr + 4);
            unsigned long long a3 = *(const unsigned long long*)(xr + 6);
            float4 bv = *(const float4*)&Cs[k * BN + nc0];
            unsigned long long b0 = splat2(bv.x);
            unsigned long long b1 = splat2(bv.y);
            unsigned long long b2 = splat2(bv.z);
            unsigned long long b3 = splat2(bv.w);
            fma2(acc[0][0], a0, b0); fma2(acc[0][1], a0, b1);
            fma2(acc[0][2], a0, b2); fma2(acc[0][3], a0, b3);
            fma2(acc[1][0], a1, b0); fma2(acc[1][1], a1, b1);
            fma2(acc[1][2], a1, b2); fma2(acc[1][3], a1, b3);
            fma2(acc[2][0], a2, b0); fma2(acc[2][1], a2, b1);
            fma2(acc[2][2], a2, b2); fma2(acc[2][3], a2, b3);
            fma2(acc[3][0], a3, b0); fma2(acc[3][1], a3, b1);
            fma2(acc[3][2], a3, b2); fma2(acc[3][3], a3, b3);
        }

        // Fold scores into running argmin (strict < keeps earliest index;
        // columns visited in ascending global index within a thread)
#pragma unroll
        for (int j = 0; j < 4; j++) {
            int n = n0 + nc0 + j;
            float cn = __ldg(&g_cnorm[n]);
#pragma unroll
            for (int i2 = 0; i2 < 4; i2++) {
                float dlo, dhi;
                unpack2(acc[i2][j], dlo, dhi);
                float slo = fmaf(-2.f, dlo, cn);
                float shi = fmaf(-2.f, dhi, cn);
                int ilo = 2 * i2, ihi = 2 * i2 + 1;
                if (slo < rmin[ilo]) { rmin[ilo] = slo; ridx[ilo] = n; }
                if (shi < rmin[ihi]) { rmin[ihi] = shi; ridx[ihi] = n; }
            }
        }
    }

    // Cross-thread reduction over the 16 tx owners of each sample row.
    __syncthreads();
    float* rs = Cs;                         // 128*16 floats (reuse Cs, 8KB)
    int*   is = (int*)(Cs + BM * 16);       // 128*16 ints  (next 8KB)
#pragma unroll
    for (int i = 0; i < 8; i++) {
        int m = m0 + i;
        rs[m * 16 + tx] = rmin[i];
        is[m * 16 + tx] = ridx[i];
    }
    __syncthreads();
    if (tid < BM) {
        int m = tid;
        float bv = rs[m * 16];
        int   bi = is[m * 16];
        for (int t = 1; t < 16; t++) {
            float v = rs[m * 16 + t];
            int   id = is[m * 16 + t];
            if (v < bv || (v == bv && id < bi)) { bv = v; bi = id; }
        }
        g_argmin[blockIdx.x * BM + m] = bi;
    }
}

// ---------- Kernel C: gather codewords + per-sample squared error ----------
__global__ void gather_kernel(const float* __restrict__ CM,
                              const float* __restrict__ X,
                              float* __restrict__ out) {
    int m = blockIdx.x;
    int d = threadIdx.x;       // 128 threads
    int idx = g_argmin[m];
    float q = CM[(size_t)d * N_EMBED + idx];
    float x = X[(size_t)m * EMBED_D + d];
    out[(size_t)m * EMBED_D + d] = q;
    float diff = q - x;
    __shared__ float sbuf[EMBED_D];
    sbuf[d] = diff * diff;
    __syncthreads();
    for (int s = 64; s > 0; s >>= 1) {
        if (d < s) sbuf[d] += sbuf[d + s];
        __syncthreads();
    }
    if (d == 0) g_partial[m] = sbuf[0];
}

// ---------- Kernel D: deterministic loss reduction ----------
__global__ void loss_kernel(float* __restrict__ out, int out_size) {
    __shared__ float sbuf[256];
    int t = threadIdx.x;
    float s = 0.f;
    // fixed per-thread sequence -> deterministic
    for (int i = 0; i < NSAMP / 256; i++) s += g_partial[t + i * 256];
    sbuf[t] = s;
    __syncthreads();
    for (int k = 128; k > 0; k >>= 1) {
        if (t < k) sbuf[t] += sbuf[t + k];
        __syncthreads();
    }
    if (t == 0)
        out[out_size - 1] = sbuf[0] * (1.25f / (float)((size_t)NSAMP * EMBED_D));
}

// ---------- launch ----------
extern "C" void kernel_launch(void* const* d_in, const int* in_sizes, int n_in,
                              void* d_out, int out_size) {
    const float* X  = (const float*)d_in[0];
    const float* CM = (const float*)d_in[1];
    // Guard against input ordering surprises: X has NSAMP*128 elems, CM 128*N_EMBED
    if (n_in >= 2 && in_sizes[0] == EMBED_D * N_EMBED &&
        in_sizes[1] == NSAMP * EMBED_D) {
        const float* t = X; X = CM; CM = t;
    }
    float* out = (float*)d_out;

    static_assert(EMBED_D * BM * 4 + EMBED_D * BN * 4 == 98304, "smem layout");
    cudaFuncSetAttribute(argmin_kernel,
                         cudaFuncAttributeMaxDynamicSharedMemorySize, 98304);

    cnorm_kernel<<<(N_PAD + 255) / 256, 256>>>(CM);
    argmin_kernel<<<NSAMP / BM, NTHREADS, 98304>>>(X, CM);
    gather_kernel<<<NSAMP, EMBED_D>>>(CM, X, out);
    loss_kernel<<<1, 256>>>(out, out_size);
}

// round 6
// speedup vs baseline: 2.0476x; 2.0476x over previous
#include <cuda_runtime.h>
#include <cuda_bf16.h>
#include <math_constants.h>
#include <cstdint>

// ---------------- problem constants ----------------
#define EMBED_D   128
#define N_EMBED   10000
#define NP2       10112          // 79 * 128
#define NTILE     79
#define NSAMP     16384
#define NCTA      128            // NSAMP / 128
#define NCAND     5

// ---------------- device scratch (no cudaMalloc allowed) ----------------
__device__ __align__(16) __nv_bfloat16 g_x1[NSAMP * EMBED_D];    // bf16(X)
__device__ __align__(16) __nv_bfloat16 g_ct1[NP2 * EMBED_D];     // bf16(C^T), n-major
__device__ __align__(16) float         g_ctf[NP2 * EMBED_D];     // fp32 C^T, n-major
__device__ __align__(16) float         g_cnorm[NP2];
__device__ int   g_cand[NSAMP * NCAND];
__device__ int   g_argmin[NSAMP];
__device__ float g_partial[NSAMP];

// ---------------- generic-PTX helpers (valid on plain sm_103) ----------------
__device__ __forceinline__ uint32_t smem_u32(const void* p) {
    uint32_t a;
    asm("{ .reg .u64 t; cvta.to.shared.u64 t, %1; cvt.u32.u64 %0, t; }" : "=r"(a) : "l"(p));
    return a;
}
__device__ __forceinline__ void cp16(uint32_t dst, const void* src) {
    asm volatile("cp.async.cg.shared.global [%0], [%1], 16;" :: "r"(dst), "l"(src));
}
__device__ __forceinline__ void cp_commit() {
    asm volatile("cp.async.commit_group;" ::: "memory");
}
template <int N>
__device__ __forceinline__ void cp_wait() {
    asm volatile("cp.async.wait_group %0;" :: "n"(N) : "memory");
}
__device__ __forceinline__ void ldsm_x4(uint32_t* r, uint32_t addr) {
    asm volatile("ldmatrix.sync.aligned.m8n8.x4.shared.b16 {%0,%1,%2,%3}, [%4];"
                 : "=r"(r[0]), "=r"(r[1]), "=r"(r[2]), "=r"(r[3]) : "r"(addr));
}
__device__ __forceinline__ void mma_bf16(float* d, const uint32_t* a,
                                         uint32_t b0, uint32_t b1) {
    asm volatile(
        "mma.sync.aligned.m16n8k16.row.col.f32.bf16.bf16.f32 "
        "{%0,%1,%2,%3}, {%4,%5,%6,%7}, {%8,%9}, {%0,%1,%2,%3};"
        : "+f"(d[0]), "+f"(d[1]), "+f"(d[2]), "+f"(d[3])
        : "r"(a[0]), "r"(a[1]), "r"(a[2]), "r"(a[3]), "r"(b0), "r"(b1));
}

// sorted top-5 insert (ascending; rare branch taken)
__device__ __forceinline__ void ins5(float s, int n, float (&v)[NCAND], int (&ii)[NCAND]) {
    if (s < v[4]) {
        if (s < v[3]) {
            v[4] = v[3]; ii[4] = ii[3];
            if (s < v[2]) {
                v[3] = v[2]; ii[3] = ii[2];
                if (s < v[1]) {
                    v[2] = v[1]; ii[2] = ii[1];
                    if (s < v[0]) { v[1] = v[0]; ii[1] = ii[0]; v[0] = s; ii[0] = n; }
                    else          { v[1] = s; ii[1] = n; }
                } else { v[2] = s; ii[2] = n; }
            } else { v[3] = s; ii[3] = n; }
        } else { v[4] = s; ii[4] = n; }
    }
}

// ---------------- precompute: bf16 quantize X ----------------
__global__ void split_x_kernel(const float* __restrict__ X) {
    int i = blockIdx.x * blockDim.x + threadIdx.x;
    g_x1[i] = __float2bfloat16(X[i]);
}

// ---------------- precompute: transpose C, bf16 + fp32 copies, norms ----------------
__global__ void split_c_kernel(const float* __restrict__ CM) {
    __shared__ float tile[EMBED_D][65];   // 64 codes per block
    int n0 = blockIdx.x * 64;
    int tid = threadIdx.x;                // 128 threads
    for (int idx = tid; idx < EMBED_D * 64; idx += 128) {
        int k = idx >> 6, n = idx & 63;
        int gn = n0 + n;
        tile[k][n] = (gn < N_EMBED) ? CM[(size_t)k * N_EMBED + gn] : 0.f;
    }
    __syncthreads();
    if (tid < 64) {
        int gn = n0 + tid;
        float s = 0.f;
        size_t base = (size_t)gn * EMBED_D;
#pragma unroll 4
        for (int k = 0; k < EMBED_D; k++) {
            float v = tile[k][tid];
            s = fmaf(v, v, s);
            g_ct1[base + k] = __float2bfloat16(v);
            g_ctf[base + k] = v;
        }
        g_cnorm[gn] = (gn < N_EMBED) ? s : CUDART_INF_F;
    }
}

// ---------------- screening GEMM: bf16 HMMA, top-5 candidates per row ----------------
// CTA: 256 thr = 8 warps, tile M=128 x N=128(per iter) x K=128.
// Warp tile M=32, N=64: wm = wid&3 (row quarter), wn = wid>>2 (col half).
#define B_STAGE  32768           // 128 codes x 128 k x bf16
#define CN_OFF   (2 * B_STAGE)   // 2 x 512B cnorm staging
#define SMEM_SZ  (2 * B_STAGE + 2 * 512)

struct Ent { float v; int i; };

__global__ __launch_bounds__(256, 1)
void screen_kernel() {
    extern __shared__ char smem[];
    const uint32_t sb = smem_u32(smem);
    const int tid = threadIdx.x;
    const int wid = tid >> 5, lid = tid & 31;
    const int wm = wid & 3, wn = wid >> 2;
    const int gr = lid >> 2, gc = (lid & 3) * 2;
    const int lr = lid & 7, lmat = lid >> 3;

    // ---- resident A fragments: rows blk*128 + wm*32 + {g*16 + gr, +8} ----
    const int m0 = blockIdx.x * 128 + wm * 32;
    uint32_t a[2][8][4];
#pragma unroll
    for (int g = 0; g < 2; g++) {
        const __nv_bfloat16* rlo = g_x1 + (size_t)(m0 + g * 16 + gr) * EMBED_D;
        const __nv_bfloat16* rhi = rlo + 8 * EMBED_D;
#pragma unroll
        for (int ks = 0; ks < 8; ks++) {
            a[g][ks][0] = *(const uint32_t*)(rlo + ks * 16 + gc);
            a[g][ks][1] = *(const uint32_t*)(rhi + ks * 16 + gc);
            a[g][ks][2] = *(const uint32_t*)(rlo + ks * 16 + gc + 8);
            a[g][ks][3] = *(const uint32_t*)(rhi + ks * 16 + gc + 8);
        }
    }

    float v[4][NCAND];
    int   ii[4][NCAND];
#pragma unroll
    for (int s = 0; s < 4; s++)
#pragma unroll
        for (int j = 0; j < NCAND; j++) { v[s][j] = CUDART_INF_F; ii[s][j] = 0; }

    // ---- B tile loader (cp.async, XOR-swizzled 16B chunks) ----
    auto loadB = [&](int t) {
        int st = t & 1;
        const __nv_bfloat16* src = g_ct1 + (size_t)t * 128 * EMBED_D;
        uint32_t dbase = sb + st * B_STAGE;
#pragma unroll
        for (int i = 0; i < 8; i++) {
            int id = tid + i * 256;          // 2048 chunks: n = id>>4, c = id&15
            int n = id >> 4, c = id & 15;
            cp16(dbase + n * 256 + (((c ^ (n & 7)) << 4)), src + n * EMBED_D + c * 8);
        }
        if (tid < 32)
            cp16(sb + CN_OFF + st * 512 + tid * 16, g_cnorm + t * 128 + tid * 4);
    };

    loadB(0); cp_commit();

    for (int t = 0; t < NTILE; t++) {
        if (t + 1 < NTILE) { loadB(t + 1); cp_commit(); cp_wait<1>(); }
        else               { cp_wait<0>(); }
        __syncthreads();

        const int st = t & 1;
        const uint32_t bbase = sb + st * B_STAGE;
        const float* cn = (const float*)(smem + CN_OFF + st * 512);

#pragma unroll
        for (int nb = 0; nb < 8; nb++) {
            const int nloc = wn * 64 + nb * 8;
            // 4x ldmatrix.x4: frag rr[g][mat] -> ks = 2g + mat/2, half mat&1
            uint32_t rr[4][4];
#pragma unroll
            for (int g = 0; g < 4; g++) {
                uint32_t addr = bbase + (uint32_t)(nloc + lr) * 256
                              + ((((g << 2) + lmat) ^ lr) << 4);
                ldsm_x4(rr[g], addr);
            }
            const float cn0 = cn[nloc + gc], cn1 = cn[nloc + gc + 1];
            const int ng = t * 128 + nloc + gc;
#pragma unroll
            for (int g2 = 0; g2 < 2; g2++) {
                float d[4] = {0.f, 0.f, 0.f, 0.f};
#pragma unroll
                for (int ks = 0; ks < 8; ks++)
                    mma_bf16(d, a[g2][ks], rr[ks >> 1][(ks & 1) * 2],
                             rr[ks >> 1][(ks & 1) * 2 + 1]);
                const int slo = g2 * 2, shi = g2 * 2 + 1;
                ins5(fmaf(-2.f, d[0], cn0), ng,     v[slo], ii[slo]);
                ins5(fmaf(-2.f, d[1], cn1), ng + 1, v[slo], ii[slo]);
                ins5(fmaf(-2.f, d[2], cn0), ng,     v[shi], ii[shi]);
                ins5(fmaf(-2.f, d[3], cn1), ng + 1, v[shi], ii[shi]);
            }
        }
        __syncthreads();
    }

    // ---- cross-lane merge: 8 contributors per row (4 quad-lanes x 2 wn) ----
    Ent* ent = (Ent*)smem;                 // [128 rows][8 slots][5]
    const int q = (wn << 2) | (lid & 3);
#pragma unroll
    for (int s = 0; s < 4; s++) {
        int rloc = wm * 32 + (s >> 1) * 16 + (s & 1) * 8 + gr;
#pragma unroll
        for (int j = 0; j < NCAND; j++)
            ent[(rloc * 8 + q) * NCAND + j] = Ent{v[s][j], ii[s][j]};
    }
    __syncthreads();
    if (tid < 128) {
        Ent* e = ent + tid * 8 * NCAND;
        int outb = (blockIdx.x * 128 + tid) * NCAND;
        for (int p = 0; p < NCAND; p++) {
            float bv = CUDART_INF_F; int bi = 0x7fffffff; int bs = -1;
            for (int s = 0; s < 8 * NCAND; s++) {
                float ev = e[s].v; int ei = e[s].i;
                if (ev < bv || (ev == bv && ei < bi)) { bv = ev; bi = ei; bs = s; }
            }
            e[bs].v = CUDART_INF_F;
            g_cand[outb + p] = bi;
        }
    }
}

// ---------------- exact fp32 refinement of the 5 candidates ----------------
__global__ void refine_kernel(const float* __restrict__ X) {
    const int wid = threadIdx.x >> 5, lid = threadIdx.x & 31;
    const int m = blockIdx.x * 8 + wid;
    float4 xv = ((const float4*)X)[(size_t)m * 32 + lid];
    float bestv = CUDART_INF_F; int besti = 0x7fffffff;
#pragma unroll
    for (int c = 0; c < NCAND; c++) {
        int j = g_cand[m * NCAND + c];
        float4 cv = ((const float4*)g_ctf)[(size_t)j * 32 + lid];
        float p = xv.x * cv.x;
        p = fmaf(xv.y, cv.y, p);
        p = fmaf(xv.z, cv.z, p);
        p = fmaf(xv.w, cv.w, p);
#pragma unroll
        for (int off = 16; off > 0; off >>= 1)
            p += __shfl_xor_sync(0xFFFFFFFF, p, off);
        float s = fmaf(-2.f, p, g_cnorm[j]);
        if (s < bestv || (s == bestv && j < besti)) { bestv = s; besti = j; }
    }
    if (lid == 0) g_argmin[m] = besti;
}

// ---------------- gather codewords + per-sample squared error ----------------
__global__ void gather_kernel(const float* __restrict__ CM,
                              const float* __restrict__ X,
                              float* __restrict__ out) {
    int m = blockIdx.x;
    int d = threadIdx.x;       // 128 threads
    int idx = g_argmin[m];
    float qv = CM[(size_t)d * N_EMBED + idx];
    float x = X[(size_t)m * EMBED_D + d];
    out[(size_t)m * EMBED_D + d] = qv;
    float diff = qv - x;
    __shared__ float sbuf[EMBED_D];
    sbuf[d] = diff * diff;
    __syncthreads();
    for (int s = 64; s > 0; s >>= 1) {
        if (d < s) sbuf[d] += sbuf[d + s];
        __syncthreads();
    }
    if (d == 0) g_partial[m] = sbuf[0];
}

// ---------------- deterministic loss reduction ----------------
__global__ void loss_kernel(float* __restrict__ out, int out_size) {
    __shared__ float sbuf[1024];
    int t = threadIdx.x;
    float s = 0.f;
    for (int i = 0; i < NSAMP / 1024; i++) s += g_partial[t + i * 1024];
    sbuf[t] = s;
    __syncthreads();
    for (int k = 512; k > 0; k >>= 1) {
        if (t < k) sbuf[t] += sbuf[t + k];
        __syncthreads();
    }
    if (t == 0)
        out[out_size - 1] = sbuf[0] * (1.25f / (float)((size_t)NSAMP * EMBED_D));
}

// ---------------- launch ----------------
extern "C" void kernel_launch(void* const* d_in, const int* in_sizes, int n_in,
                              void* d_out, int out_size) {
    const float* X  = (const float*)d_in[0];
    const float* CM = (const float*)d_in[1];
    if (n_in >= 2 && in_sizes[0] == EMBED_D * N_EMBED &&
        in_sizes[1] == NSAMP * EMBED_D) {
        const float* t = X; X = CM; CM = t;
    }
    float* out = (float*)d_out;

    cudaFuncSetAttribute(screen_kernel,
                         cudaFuncAttributeMaxDynamicSharedMemorySize, SMEM_SZ);

    split_x_kernel<<<NSAMP * EMBED_D / 256, 256>>>(X);
    split_c_kernel<<<NP2 / 64, 128>>>(CM);
    screen_kernel<<<NCTA, 256, SMEM_SZ>>>();
    refine_kernel<<<NSAMP / 8, 256>>>(X);
    gather_kernel<<<NSAMP, EMBED_D>>>(CM, X, out);
    loss_kernel<<<1, 1024>>>(out, out_size);
}

// round 7
// speedup vs baseline: 2.1617x; 1.0557x over previous
#include <cuda_runtime.h>
#include <cuda_bf16.h>
#include <math_constants.h>
#include <cstdint>

// ---------------- problem constants ----------------
#define EMBED_D   128
#define N_EMBED   10000
#define NP2       10112          // 79 * 128
#define NTILE     79
#define NSAMP     16384
#define NCAND     5
#define SQ        32.0f          // int8 quant scale
#define NEG2      (-2.0f / (SQ * SQ))

// ---------------- device scratch (no cudaMalloc allowed) ----------------
__device__ __align__(16) int8_t g_x8[NSAMP * EMBED_D];    // int8 X
__device__ __align__(16) int8_t g_ct8[NP2 * EMBED_D];     // int8 C^T, n-major
__device__ __align__(16) float  g_ctf[NP2 * EMBED_D];     // fp32 C^T, n-major (exact copy)
__device__ __align__(16) float  g_cnorm[NP2];
__device__ int   g_cand[NSAMP * 2 * NCAND];
__device__ float g_partial[NSAMP];

// ---------------- generic-PTX helpers (valid on plain sm_103) ----------------
__device__ __forceinline__ uint32_t smem_u32(const void* p) {
    uint32_t a;
    asm("{ .reg .u64 t; cvta.to.shared.u64 t, %1; cvt.u32.u64 %0, t; }" : "=r"(a) : "l"(p));
    return a;
}
__device__ __forceinline__ void cp16(uint32_t dst, const void* src) {
    asm volatile("cp.async.cg.shared.global [%0], [%1], 16;" :: "r"(dst), "l"(src));
}
__device__ __forceinline__ void cp_commit() {
    asm volatile("cp.async.commit_group;" ::: "memory");
}
template <int N>
__device__ __forceinline__ void cp_wait() {
    asm volatile("cp.async.wait_group %0;" :: "n"(N) : "memory");
}
__device__ __forceinline__ int lds32(uint32_t addr) {
    int v;
    asm volatile("ld.shared.b32 %0, [%1];" : "=r"(v) : "r"(addr));
    return v;
}
__device__ __forceinline__ void mma_s8(int* d, const int* a, int b0, int b1) {
    asm volatile(
        "mma.sync.aligned.m16n8k32.row.col.s32.s8.s8.s32 "
        "{%0,%1,%2,%3}, {%4,%5,%6,%7}, {%8,%9}, {%0,%1,%2,%3};"
        : "+r"(d[0]), "+r"(d[1]), "+r"(d[2]), "+r"(d[3])
        : "r"(a[0]), "r"(a[1]), "r"(a[2]), "r"(a[3]), "r"(b0), "r"(b1));
}
__device__ __forceinline__ int8_t q8(float v) {
    int i = __float2int_rn(v * SQ);
    i = max(-127, min(127, i));
    return (int8_t)i;
}

// sorted top-5 insert (ascending; outer test rarely true)
__device__ __forceinline__ void ins5(float s, int n, float (&v)[NCAND], int (&ii)[NCAND]) {
    if (s < v[4]) {
        if (s < v[3]) {
            v[4] = v[3]; ii[4] = ii[3];
            if (s < v[2]) {
                v[3] = v[2]; ii[3] = ii[2];
                if (s < v[1]) {
                    v[2] = v[1]; ii[2] = ii[1];
                    if (s < v[0]) { v[1] = v[0]; ii[1] = ii[0]; v[0] = s; ii[0] = n; }
                    else          { v[1] = s; ii[1] = n; }
                } else { v[2] = s; ii[2] = n; }
            } else { v[3] = s; ii[3] = n; }
        } else { v[4] = s; ii[4] = n; }
    }
}

// ---------------- precompute: int8 quantize X ----------------
__global__ void split_x_kernel(const float* __restrict__ X) {
    int i = blockIdx.x * blockDim.x + threadIdx.x;   // per float4
    float4 v = ((const float4*)X)[i];
    char4 p;
    p.x = q8(v.x); p.y = q8(v.y); p.z = q8(v.z); p.w = q8(v.w);
    ((char4*)g_x8)[i] = p;
}

// ---------------- precompute: transpose C -> int8 + fp32 + norms (coalesced) ----------------
__global__ void split_c_kernel(const float* __restrict__ CM) {
    __shared__ float tile[EMBED_D][65];   // 64 codes per block
    int n0 = blockIdx.x * 64;
    int tid = threadIdx.x;                // 128 threads
    for (int idx = tid; idx < EMBED_D * 64; idx += 128) {
        int k = idx >> 6, n = idx & 63;
        int gn = n0 + n;
        tile[k][n] = (gn < N_EMBED) ? CM[(size_t)k * N_EMBED + gn] : 0.f;
    }
    __syncthreads();
    if (tid < 64) {
        int gn = n0 + tid;
        float s = 0.f;
#pragma unroll 8
        for (int k = 0; k < EMBED_D; k++) {
            float v = tile[k][tid];
            s = fmaf(v, v, s);
        }
        g_cnorm[gn] = (gn < N_EMBED) ? s : CUDART_INF_F;
    }
    // fp32 transpose out, coalesced (consecutive tid -> consecutive k)
    for (int idx = tid; idx < 64 * EMBED_D; idx += 128) {
        int n = idx >> 7, k = idx & 127;
        g_ctf[(size_t)(n0 + n) * EMBED_D + k] = tile[k][n];
    }
    // int8 transpose out, coalesced char4
    for (int idx = tid; idx < 64 * 32; idx += 128) {
        int n = idx >> 5, w = idx & 31;
        char4 p;
        p.x = q8(tile[4 * w + 0][n]);
        p.y = q8(tile[4 * w + 1][n]);
        p.z = q8(tile[4 * w + 2][n]);
        p.w = q8(tile[4 * w + 3][n]);
        ((char4*)g_ct8)[(size_t)(n0 + n) * 32 + w] = p;
    }
}

// ---------------- screening GEMM: int8 IMMA, top-5 candidates per lane ----------------
// Grid 256 = 128 M-tiles x 2 N-halves. CTA: 8 warps, warp tile M=32 N=64, N=128/iter.
#define B_STAGE  16384           // 128 codes x 128 int8
#define CN_OFF   (2 * B_STAGE)
#define SMEM_SZ  (2 * B_STAGE + 2 * 512)   // 33792

struct Ent { float v; int i; };

__global__ __launch_bounds__(256, 2)
void screen_kernel() {
    extern __shared__ char smem[];
    const uint32_t sb = smem_u32(smem);
    const int tid = threadIdx.x;
    const int wid = tid >> 5, lid = tid & 31;
    const int wm = wid & 3, wn = wid >> 2;
    const int gr = lid >> 2, q = lid & 3;
    const int mb = blockIdx.x >> 1, nh = blockIdx.x & 1;
    const int t0 = nh ? 40 : 0;
    const int ntl = nh ? 39 : 40;

    // ---- resident A fragments (int8): rows mb*128 + wm*32 + g2*16 + {gr, gr+8} ----
    const int8_t* xb = g_x8 + (size_t)(mb * 128 + wm * 32) * EMBED_D;
    int a[2][4][4];
#pragma unroll
    for (int g2 = 0; g2 < 2; g2++)
#pragma unroll
        for (int ks = 0; ks < 4; ks++) {
            const int8_t* r0 = xb + (g2 * 16 + gr) * EMBED_D + ks * 32 + q * 4;
            a[g2][ks][0] = *(const int*)(r0);
            a[g2][ks][1] = *(const int*)(r0 + 8 * EMBED_D);
            a[g2][ks][2] = *(const int*)(r0 + 16);
            a[g2][ks][3] = *(const int*)(r0 + 8 * EMBED_D + 16);
        }

    float v[4][NCAND];
    int   ii[4][NCAND];
#pragma unroll
    for (int s = 0; s < 4; s++)
#pragma unroll
        for (int j = 0; j < NCAND; j++) { v[s][j] = CUDART_INF_F; ii[s][j] = 0; }

    // ---- B loader: XOR-swizzled 16B chunks (8 chunks per 128B row) ----
    auto loadB = [&](int t, int st) {
        const int8_t* src = g_ct8 + (size_t)t * 128 * EMBED_D;
        uint32_t db = sb + st * B_STAGE;
#pragma unroll
        for (int i = 0; i < 4; i++) {
            int id = tid + i * 256;          // 1024 chunks
            int n = id >> 3, c = id & 7;
            cp16(db + n * 128 + (((c ^ (n & 7)) << 4)), src + n * EMBED_D + c * 16);
        }
        if (tid < 32)
            cp16(sb + CN_OFF + st * 512 + tid * 16, g_cnorm + t * 128 + tid * 4);
    };

    loadB(t0, 0); cp_commit();

    for (int i = 0; i < ntl; i++) {
        if (i + 1 < ntl) { loadB(t0 + i + 1, (i + 1) & 1); cp_commit(); cp_wait<1>(); }
        else             { cp_wait<0>(); }
        __syncthreads();

        const int t = t0 + i;
        const int st = i & 1;
        const uint32_t bbase = sb + st * B_STAGE;
        const float* cn = (const float*)(smem + CN_OFF + st * 512);

#pragma unroll
        for (int nb = 0; nb < 8; nb++) {
            const int nloc = wn * 64 + nb * 8;
            const uint32_t rowb = bbase + (uint32_t)(nloc + gr) * 128 + q * 4;
            int b[4][2];
#pragma unroll
            for (int ks = 0; ks < 4; ks++) {
                b[ks][0] = lds32(rowb + ((uint32_t)((2 * ks)     ^ gr) << 4));
                b[ks][1] = lds32(rowb + ((uint32_t)((2 * ks + 1) ^ gr) << 4));
            }
            const float cn0 = cn[nloc + 2 * q], cn1 = cn[nloc + 2 * q + 1];
            const int ng = t * 128 + nloc + 2 * q;
#pragma unroll
            for (int g2 = 0; g2 < 2; g2++) {
                int d[4] = {0, 0, 0, 0};
#pragma unroll
                for (int ks = 0; ks < 4; ks++)
                    mma_s8(d, a[g2][ks], b[ks][0], b[ks][1]);
                const int slo = g2 * 2, shi = g2 * 2 + 1;
                ins5(fmaf(NEG2, (float)d[0], cn0), ng,     v[slo], ii[slo]);
                ins5(fmaf(NEG2, (float)d[1], cn1), ng + 1, v[slo], ii[slo]);
                ins5(fmaf(NEG2, (float)d[2], cn0), ng,     v[shi], ii[shi]);
                ins5(fmaf(NEG2, (float)d[3], cn1), ng + 1, v[shi], ii[shi]);
            }
        }
        __syncthreads();
    }

    // ---- merge: 8 contributors/row, 2 phases of 64 rows (smem = 20KB/phase) ----
    Ent* ent = (Ent*)smem;                 // [64 rows][8 slots][5]
    const int q8s = (wn << 2) | q;
    for (int p = 0; p < 2; p++) {
        __syncthreads();
        if ((wm >> 1) == p) {
#pragma unroll
            for (int s = 0; s < 4; s++) {
                int rloc = (wm & 1) * 32 + (s >> 1) * 16 + (s & 1) * 8 + gr;
#pragma unroll
                for (int j = 0; j < NCAND; j++)
                    ent[(rloc * 8 + q8s) * NCAND + j] = Ent{v[s][j], ii[s][j]};
            }
        }
        __syncthreads();
        if (tid < 64) {
            Ent* e = ent + tid * 8 * NCAND;
            int m = mb * 128 + p * 64 + tid;
            int outb = m * (2 * NCAND) + nh * NCAND;
            for (int pc = 0; pc < NCAND; pc++) {
                float bv = CUDART_INF_F; int bi = 0x7fffffff; int bs = 0;
                for (int s = 0; s < 8 * NCAND; s++) {
                    float ev = e[s].v; int ei = e[s].i;
                    if (ev < bv || (ev == bv && ei < bi)) { bv = ev; bi = ei; bs = s; }
                }
                e[bs].v = CUDART_INF_F;
                g_cand[outb + pc] = bi;
            }
        }
    }
}

// ---------------- exact fp32 refinement + output + per-row error (fused gather) ----------------
__global__ void refine_kernel(const float* __restrict__ X, float* __restrict__ out) {
    const int wid = threadIdx.x >> 5, lid = threadIdx.x & 31;
    const int m = blockIdx.x * 8 + wid;
    float4 xv = ((const float4*)X)[(size_t)m * 32 + lid];
    float bestv = CUDART_INF_F; int besti = 0x7fffffff;
#pragma unroll
    for (int c = 0; c < 2 * NCAND; c++) {
        int j = g_cand[m * (2 * NCAND) + c];
        float4 cv = ((const float4*)g_ctf)[(size_t)j * 32 + lid];
        float p = xv.x * cv.x;
        p = fmaf(xv.y, cv.y, p);
        p = fmaf(xv.z, cv.z, p);
        p = fmaf(xv.w, cv.w, p);
#pragma unroll
        for (int off = 16; off > 0; off >>= 1)
            p += __shfl_xor_sync(0xFFFFFFFF, p, off);
        float s = fmaf(-2.f, p, g_cnorm[j]);
        if (s < bestv || (s == bestv && j < besti)) { bestv = s; besti = j; }
    }
    // fused gather: write quantized row + squared error
    float4 cv = ((const float4*)g_ctf)[(size_t)besti * 32 + lid];
    ((float4*)out)[(size_t)m * 32 + lid] = cv;
    float dx = cv.x - xv.x, dy = cv.y - xv.y, dz = cv.z - xv.z, dw = cv.w - xv.w;
    float e = dx * dx + dy * dy + dz * dz + dw * dw;
#pragma unroll
    for (int off = 16; off > 0; off >>= 1)
        e += __shfl_xor_sync(0xFFFFFFFF, e, off);
    if (lid == 0) g_partial[m] = e;
}

// ---------------- deterministic loss reduction ----------------
__global__ void loss_kernel(float* __restrict__ out, int out_size) {
    __shared__ float sbuf[1024];
    int t = threadIdx.x;
    float s = 0.f;
    for (int i = 0; i < NSAMP / 1024; i++) s += g_partial[t + i * 1024];
    sbuf[t] = s;
    __syncthreads();
    for (int k = 512; k > 0; k >>= 1) {
        if (t < k) sbuf[t] += sbuf[t + k];
        __syncthreads();
    }
    if (t == 0)
        out[out_size - 1] = sbuf[0] * (1.25f / (float)((size_t)NSAMP * EMBED_D));
}

// ---------------- launch ----------------
extern "C" void kernel_launch(void* const* d_in, const int* in_sizes, int n_in,
                              void* d_out, int out_size) {
    const float* X  = (const float*)d_in[0];
    const float* CM = (const float*)d_in[1];
    if (n_in >= 2 && in_sizes[0] == EMBED_D * N_EMBED &&
        in_sizes[1] == NSAMP * EMBED_D) {
        const float* t = X; X = CM; CM = t;
    }
    float* out = (float*)d_out;

    cudaFuncSetAttribute(screen_kernel,
                         cudaFuncAttributeMaxDynamicSharedMemorySize, SMEM_SZ);

    split_x_kernel<<<NSAMP * EMBED_D / 4 / 256, 256>>>(X);
    split_c_kernel<<<NP2 / 64, 128>>>(CM);
    screen_kernel<<<256, 256, SMEM_SZ>>>();
    refine_kernel<<<NSAMP / 8, 256>>>(X, out);
    loss_kernel<<<1, 1024>>>(out, out_size);
}

// round 9
// speedup vs baseline: 2.5400x; 1.1750x over previous
#include <cuda_runtime.h>
#include <math_constants.h>
#include <cstdint>

// ---------------- problem constants ----------------
#define EMBED_D   128
#define N_EMBED   10000
#define NP2       10112          // 79 * 128
#define NTILE     79
#define NSAMP     16384
#define NSEL      4              // candidates kept per (row, N-third)
#define NREF      12             // 3 thirds * NSEL
#define SQ        32.0f          // int8 quant scale
#define ICN_SC    512.0f         // = SQ*SQ/2 : score_int = icn - d

// ---------------- device scratch (no cudaMalloc allowed) ----------------
__device__ __align__(16) int8_t g_x8[NSAMP * EMBED_D];    // int8 X
__device__ __align__(16) int8_t g_ct8[NP2 * EMBED_D];     // int8 C^T, n-major
__device__ __align__(16) float  g_ctf[NP2 * EMBED_D];     // fp32 C^T, n-major (exact)
__device__ __align__(16) float  g_cnorm[NP2];             // exact fp32 norms
__device__ __align__(16) int    g_icn[NP2];               // round(512 * norm), pad=1<<30
__device__ int   g_cand[NSAMP * NREF];
__device__ float g_partial[NSAMP];

// ---------------- generic-PTX helpers (plain sm_103 safe) ----------------
__device__ __forceinline__ uint32_t smem_u32(const void* p) {
    uint32_t a;
    asm("{ .reg .u64 t; cvta.to.shared.u64 t, %1; cvt.u32.u64 %0, t; }" : "=r"(a) : "l"(p));
    return a;
}
__device__ __forceinline__ void cp16(uint32_t dst, const void* src) {
    asm volatile("cp.async.cg.shared.global [%0], [%1], 16;" :: "r"(dst), "l"(src));
}
__device__ __forceinline__ void cp_commit() {
    asm volatile("cp.async.commit_group;" ::: "memory");
}
template <int N>
__device__ __forceinline__ void cp_wait() {
    asm volatile("cp.async.wait_group %0;" :: "n"(N) : "memory");
}
__device__ __forceinline__ int lds32(uint32_t addr) {
    int v;
    asm volatile("ld.shared.b32 %0, [%1];" : "=r"(v) : "r"(addr));
    return v;
}
__device__ __forceinline__ int2 lds64(uint32_t addr) {
    int2 v;
    asm volatile("ld.shared.v2.b32 {%0,%1}, [%2];" : "=r"(v.x), "=r"(v.y) : "r"(addr));
    return v;
}
__device__ __forceinline__ void mma_s8(int* d, const int* a, int b0, int b1) {
    asm volatile(
        "mma.sync.aligned.m16n8k32.row.col.s32.s8.s8.s32 "
        "{%0,%1,%2,%3}, {%4,%5,%6,%7}, {%8,%9}, {%0,%1,%2,%3};"
        : "+r"(d[0]), "+r"(d[1]), "+r"(d[2]), "+r"(d[3])
        : "r"(a[0]), "r"(a[1]), "r"(a[2]), "r"(a[3]), "r"(b0), "r"(b1));
}
__device__ __forceinline__ int8_t q8(float v) {
    int i = __float2int_rn(v * SQ);
    i = max(-127, min(127, i));
    return (int8_t)i;
}

// top-2 insert, integer scores (outer test rarely true)
__device__ __forceinline__ void ins2(int s, int n, int (&v)[2], int (&ii)[2]) {
    if (s < v[1]) {
        if (s < v[0]) { v[1] = v[0]; ii[1] = ii[0]; v[0] = s; ii[0] = n; }
        else          { v[1] = s; ii[1] = n; }
    }
}

// ---------------- precompute: int8 quantize X ----------------
__global__ void split_x_kernel(const float* __restrict__ X) {
    int i = blockIdx.x * blockDim.x + threadIdx.x;   // per float4
    float4 v = ((const float4*)X)[i];
    char4 p;
    p.x = q8(v.x); p.y = q8(v.y); p.z = q8(v.z); p.w = q8(v.w);
    ((char4*)g_x8)[i] = p;
}

// ---------------- precompute: transpose C -> int8 + fp32 + norms ----------------
__global__ void split_c_kernel(const float* __restrict__ CM) {
    __shared__ float tile[EMBED_D][65];   // 64 codes per block
    int n0 = blockIdx.x * 64;
    int tid = threadIdx.x;                // 128 threads
    for (int idx = tid; idx < EMBED_D * 64; idx += 128) {
        int k = idx >> 6, n = idx & 63;
        int gn = n0 + n;
        tile[k][n] = (gn < N_EMBED) ? CM[(size_t)k * N_EMBED + gn] : 0.f;
    }
    __syncthreads();
    if (tid < 64) {
        int gn = n0 + tid;
        float s = 0.f;
#pragma unroll 8
        for (int k = 0; k < EMBED_D; k++) {
            float v = tile[k][tid];
            s = fmaf(v, v, s);
        }
        if (gn < N_EMBED) {
            g_cnorm[gn] = s;
            g_icn[gn] = __float2int_rn(s * ICN_SC);
        } else {
            g_cnorm[gn] = CUDART_INF_F;
            g_icn[gn] = 1 << 30;
        }
    }
    // fp32 transpose out, coalesced
    for (int idx = tid; idx < 64 * EMBED_D; idx += 128) {
        int n = idx >> 7, k = idx & 127;
        g_ctf[(size_t)(n0 + n) * EMBED_D + k] = tile[k][n];
    }
    // int8 transpose out, coalesced char4
    for (int idx = tid; idx < 64 * 32; idx += 128) {
        int n = idx >> 5, w = idx & 31;
        char4 p;
        p.x = q8(tile[4 * w + 0][n]);
        p.y = q8(tile[4 * w + 1][n]);
        p.z = q8(tile[4 * w + 2][n]);
        p.w = q8(tile[4 * w + 3][n]);
        ((char4*)g_ct8)[(size_t)(n0 + n) * 32 + w] = p;
    }
}

// ---------------- screening GEMM: int8 IMMA, int top-2/lane -> top-4/row/third ----
// Grid 384 = 128 M-tiles x 3 N-thirds. CTA 256 thr, occ 3. Warp tile M=32 N=64.
#define B_STAGE  16384           // 128 codes x 128 int8
#define CN_OFF   (2 * B_STAGE)
#define SMEM_SZ  (2 * B_STAGE + 2 * 512)   // 33792

struct Ent { int v; int i; };

__global__ __launch_bounds__(256, 3)
void screen_kernel() {
    extern __shared__ char smem[];
    const uint32_t sb = smem_u32(smem);
    const int tid = threadIdx.x;
    const int wid = tid >> 5, lid = tid & 31;
    const int wm = wid & 3, wn = wid >> 2;
    const int gr = lid >> 2, q = lid & 3;
    const int mb = blockIdx.x / 3, nh = blockIdx.x % 3;
    const int t0  = (nh == 0) ? 0 : (nh == 1 ? 27 : 53);
    const int ntl = (nh == 0) ? 27 : 26;

    // ---- resident A fragments (int8): rows mb*128 + wm*32 + g2*16 + {gr, gr+8} ----
    const int8_t* xb = g_x8 + (size_t)(mb * 128 + wm * 32) * EMBED_D;
    int a[2][4][4];
#pragma unroll
    for (int g2 = 0; g2 < 2; g2++)
#pragma unroll
        for (int ks = 0; ks < 4; ks++) {
            const int8_t* r0 = xb + (g2 * 16 + gr) * EMBED_D + ks * 32 + q * 4;
            a[g2][ks][0] = *(const int*)(r0);
            a[g2][ks][1] = *(const int*)(r0 + 8 * EMBED_D);
            a[g2][ks][2] = *(const int*)(r0 + 16);
            a[g2][ks][3] = *(const int*)(r0 + 8 * EMBED_D + 16);
        }

    int v[4][2], ii[4][2];
#pragma unroll
    for (int s = 0; s < 4; s++) {
        v[s][0] = v[s][1] = 0x7fffffff;
        ii[s][0] = ii[s][1] = 0;
    }

    // ---- B loader: XOR-swizzled 16B chunks ----
    auto loadB = [&](int t, int st) {
        const int8_t* src = g_ct8 + (size_t)t * 128 * EMBED_D;
        uint32_t db = sb + st * B_STAGE;
#pragma unroll
        for (int i = 0; i < 4; i++) {
            int id = tid + i * 256;          // 1024 chunks
            int n = id >> 3, c = id & 7;
            cp16(db + n * 128 + (((c ^ (n & 7)) << 4)), src + n * EMBED_D + c * 16);
        }
        if (tid < 32)
            cp16(sb + CN_OFF + st * 512 + tid * 16, g_icn + t * 128 + tid * 4);
    };

    loadB(t0, 0); cp_commit();

    for (int i = 0; i < ntl; i++) {
        if (i + 1 < ntl) { loadB(t0 + i + 1, (i + 1) & 1); cp_commit(); cp_wait<1>(); }
        else             { cp_wait<0>(); }
        __syncthreads();

        const int t = t0 + i;
        const int st = i & 1;
        const uint32_t bbase = sb + st * B_STAGE;
        const uint32_t cnb = sb + CN_OFF + st * 512;

#pragma unroll
        for (int nb = 0; nb < 8; nb++) {
            const int nloc = wn * 64 + nb * 8;
            const uint32_t rowb = bbase + (uint32_t)(nloc + gr) * 128 + q * 4;
            int b[4][2];
#pragma unroll
            for (int ks = 0; ks < 4; ks++) {
                b[ks][0] = lds32(rowb + ((uint32_t)((2 * ks)     ^ gr) << 4));
                b[ks][1] = lds32(rowb + ((uint32_t)((2 * ks + 1) ^ gr) << 4));
            }
            const int2 icn = lds64(cnb + (uint32_t)(nloc + 2 * q) * 4);
            const int ng = t * 128 + nloc + 2 * q;
#pragma unroll
            for (int g2 = 0; g2 < 2; g2++) {
                int d[4] = {0, 0, 0, 0};
#pragma unroll
                for (int ks = 0; ks < 4; ks++)
                    mma_s8(d, a[g2][ks], b[ks][0], b[ks][1]);
                const int slo = g2 * 2, shi = g2 * 2 + 1;
                ins2(icn.x - d[0], ng,     v[slo], ii[slo]);
                ins2(icn.y - d[1], ng + 1, v[slo], ii[slo]);
                ins2(icn.x - d[2], ng,     v[shi], ii[shi]);
                ins2(icn.y - d[3], ng + 1, v[shi], ii[shi]);
            }
        }
        __syncthreads();
    }

    // ---- merge: 16 entries/row (8 contributors x 2) -> top-4; 2 phases of 64 rows ----
    Ent* ent = (Ent*)smem;                 // [64 rows][16]
    const int q8s = (wn << 2) | q;
    for (int p = 0; p < 2; p++) {
        __syncthreads();
        if ((wm >> 1) == p) {
#pragma unroll
            for (int s = 0; s < 4; s++) {
                int rloc = (wm & 1) * 32 + (s >> 1) * 16 + (s & 1) * 8 + gr;
#pragma unroll
                for (int j = 0; j < 2; j++)
                    ent[rloc * 16 + q8s * 2 + j] = Ent{v[s][j], ii[s][j]};
            }
        }
        __syncthreads();
        if (tid < 64) {
            Ent* e = ent + tid * 16;
            int m = mb * 128 + p * 64 + tid;
            int outb = m * NREF + nh * NSEL;
            for (int pc = 0; pc < NSEL; pc++) {
                int bv = 0x7fffffff, bi = 0x7fffffff, bs = 0;
                for (int s = 0; s < 16; s++) {
                    int ev = e[s].v, ei = e[s].i;
                    if (ev < bv || (ev == bv && ei < bi)) { bv = ev; bi = ei; bs = s; }
                }
                e[bs].v = 0x7fffffff;
                g_cand[outb + pc] = bi;
            }
        }
    }
}

// ---------------- exact fp32 refinement + fused gather / error ----------------
__global__ void refine_kernel(const float* __restrict__ X, float* __restrict__ out) {
    const int wid = threadIdx.x >> 5, lid = threadIdx.x & 31;
    const int m = blockIdx.x * 8 + wid;
    float4 xv = ((const float4*)X)[(size_t)m * 32 + lid];
    float bestv = CUDART_INF_F; int besti = 0x7fffffff;
#pragma unroll
    for (int c = 0; c < NREF; c++) {
        int j = g_cand[m * NREF + c];
        float4 cv = ((const float4*)g_ctf)[(size_t)j * 32 + lid];
        float p = xv.x * cv.x;
        p = fmaf(xv.y, cv.y, p);
        p = fmaf(xv.z, cv.z, p);
        p = fmaf(xv.w, cv.w, p);
#pragma unroll
        for (int off = 16; off > 0; off >>= 1)
            p += __shfl_xor_sync(0xFFFFFFFF, p, off);
        float s = fmaf(-2.f, p, g_cnorm[j]);
        if (s < bestv || (s == bestv && j < besti)) { bestv = s; besti = j; }
    }
    float4 cv = ((const float4*)g_ctf)[(size_t)besti * 32 + lid];
    ((float4*)out)[(size_t)m * 32 + lid] = cv;
    float dx = cv.x - xv.x, dy = cv.y - xv.y, dz = cv.z - xv.z, dw = cv.w - xv.w;
    float e = dx * dx + dy * dy + dz * dz + dw * dw;
#pragma unroll
    for (int off = 16; off > 0; off >>= 1)
        e += __shfl_xor_sync(0xFFFFFFFF, e, off);
    if (lid == 0) g_partial[m] = e;
}

// ---------------- deterministic loss reduction ----------------
__global__ void loss_kernel(float* __restrict__ out, int out_size) {
    __shared__ float sbuf[1024];
    int t = threadIdx.x;
    float s = 0.f;
    for (int i = 0; i < NSAMP / 1024; i++) s += g_partial[t + i * 1024];
    sbuf[t] = s;
    __syncthreads();
    for (int k = 512; k > 0; k >>= 1) {
        if (t < k) sbuf[t] += sbuf[t + k];
        __syncthreads();
    }
    if (t == 0)
        out[out_size - 1] = sbuf[0] * (1.25f / (float)((size_t)NSAMP * EMBED_D));
}

// ---------------- launch ----------------
extern "C" void kernel_launch(void* const* d_in, const int* in_sizes, int n_in,
                              void* d_out, int out_size) {
    const float* X  = (const float*)d_in[0];
    const float* CM = (const float*)d_in[1];
    if (n_in >= 2 && in_sizes[0] == EMBED_D * N_EMBED &&
        in_sizes[1] == NSAMP * EMBED_D) {
        const float* t = X; X = CM; CM = t;
    }
    float* out = (float*)d_out;

    cudaFuncSetAttribute(screen_kernel,
                         cudaFuncAttributeMaxDynamicSharedMemorySize, SMEM_SZ);

    split_x_kernel<<<NSAMP * EMBED_D / 4 / 256, 256>>>(X);
    split_c_kernel<<<NP2 / 64, 128>>>(CM);
    screen_kernel<<<384, 256, SMEM_SZ>>>();
    refine_kernel<<<NSAMP / 8, 256>>>(X, out);
    loss_kernel<<<1, 1024>>>(out, out_size);
}

// round 11
// speedup vs baseline: 2.8634x; 1.1273x over previous
#include <cuda_runtime.h>
#include <math_constants.h>
#include <cstdint>

// ---------------- problem constants ----------------
#define EMBED_D   128
#define N_EMBED   10000
#define NP2       10112          // 79 * 128
#define NSAMP     16384
#define NSEL      4              // candidates kept per (row, N-third)
#define NREF      12             // 3 thirds * NSEL
#define SQ        32.0f          // int8 quant scale
#define ICN_SC    512.0f         // = SQ*SQ/2 : score_int = icn - d

// ---------------- device scratch (no cudaMalloc allowed) ----------------
__device__ __align__(16) int8_t g_x8[NSAMP * EMBED_D];    // int8 X
__device__ __align__(16) int8_t g_ct8[NP2 * EMBED_D];     // int8 C^T, n-major
__device__ __align__(16) float  g_ctf[NP2 * EMBED_D];     // fp32 C^T, n-major (exact)
__device__ __align__(16) float  g_cnorm[NP2];             // exact fp32 norms
__device__ __align__(16) int    g_icn[NP2];               // round(512*norm), pad=1<<30
__device__ int   g_cand[NSAMP * NREF];
__device__ float g_partial[NSAMP];

// ---------------- generic-PTX helpers (plain sm_103 safe) ----------------
__device__ __forceinline__ uint32_t smem_u32(const void* p) {
    uint32_t a;
    asm("{ .reg .u64 t; cvta.to.shared.u64 t, %1; cvt.u32.u64 %0, t; }" : "=r"(a) : "l"(p));
    return a;
}
__device__ __forceinline__ void cp16(uint32_t dst, const void* src) {
    asm volatile("cp.async.cg.shared.global [%0], [%1], 16;" :: "r"(dst), "l"(src));
}
__device__ __forceinline__ void cp_commit() {
    asm volatile("cp.async.commit_group;" ::: "memory");
}
template <int N>
__device__ __forceinline__ void cp_wait() {
    asm volatile("cp.async.wait_group %0;" :: "n"(N) : "memory");
}
__device__ __forceinline__ int lds32(uint32_t addr) {
    int v;
    asm volatile("ld.shared.b32 %0, [%1];" : "=r"(v) : "r"(addr));
    return v;
}
__device__ __forceinline__ int2 lds64(uint32_t addr) {
    int2 v;
    asm volatile("ld.shared.v2.b32 {%0,%1}, [%2];" : "=r"(v.x), "=r"(v.y) : "r"(addr));
    return v;
}
__device__ __forceinline__ void mma_s8(int* d, const int* a, int b0, int b1) {
    asm volatile(
        "mma.sync.aligned.m16n8k32.row.col.s32.s8.s8.s32 "
        "{%0,%1,%2,%3}, {%4,%5,%6,%7}, {%8,%9}, {%0,%1,%2,%3};"
        : "+r"(d[0]), "+r"(d[1]), "+r"(d[2]), "+r"(d[3])
        : "r"(a[0]), "r"(a[1]), "r"(a[2]), "r"(a[3]), "r"(b0), "r"(b1));
}
__device__ __forceinline__ void dp4a(int& acc, int a, int b) {
    asm volatile("dp4a.s32.s32 %0, %1, %2, %0;" : "+r"(acc) : "r"(a), "r"(b));
}
__device__ __forceinline__ int8_t q8(float v) {
    int i = __float2int_rn(v * SQ);
    i = max(-127, min(127, i));
    return (int8_t)i;
}

// top-2 insert, integer scores (outer test rarely true)
__device__ __forceinline__ void ins2(int s, int n, int (&v)[2], int (&ii)[2]) {
    if (s < v[1]) {
        if (s < v[0]) { v[1] = v[0]; ii[1] = ii[0]; v[0] = s; ii[0] = n; }
        else          { v[1] = s; ii[1] = n; }
    }
}

// ---------------- precompute: int8 quantize X ----------------
__global__ void split_x_kernel(const float* __restrict__ X) {
    int i = blockIdx.x * blockDim.x + threadIdx.x;   // per float4
    float4 v = ((const float4*)X)[i];
    char4 p;
    p.x = q8(v.x); p.y = q8(v.y); p.z = q8(v.z); p.w = q8(v.w);
    ((char4*)g_x8)[i] = p;
}

// ---------------- precompute: transpose C -> int8 + fp32 + norms ----------------
__global__ void split_c_kernel(const float* __restrict__ CM) {
    __shared__ float tile[EMBED_D][65];   // 64 codes per block
    int n0 = blockIdx.x * 64;
    int tid = threadIdx.x;                // 128 threads
    for (int idx = tid; idx < EMBED_D * 64; idx += 128) {
        int k = idx >> 6, n = idx & 63;
        int gn = n0 + n;
        tile[k][n] = (gn < N_EMBED) ? CM[(size_t)k * N_EMBED + gn] : 0.f;
    }
    __syncthreads();
    if (tid < 64) {
        int gn = n0 + tid;
        float s = 0.f;
#pragma unroll 8
        for (int k = 0; k < EMBED_D; k++) {
            float v = tile[k][tid];
            s = fmaf(v, v, s);
        }
        if (gn < N_EMBED) {
            g_cnorm[gn] = s;
            g_icn[gn] = __float2int_rn(s * ICN_SC);
        } else {
            g_cnorm[gn] = CUDART_INF_F;
            g_icn[gn] = 1 << 30;
        }
    }
    for (int idx = tid; idx < 64 * EMBED_D; idx += 128) {
        int n = idx >> 7, k = idx & 127;
        g_ctf[(size_t)(n0 + n) * EMBED_D + k] = tile[k][n];
    }
    for (int idx = tid; idx < 64 * 32; idx += 128) {
        int n = idx >> 5, w = idx & 31;
        char4 p;
        p.x = q8(tile[4 * w + 0][n]);
        p.y = q8(tile[4 * w + 1][n]);
        p.z = q8(tile[4 * w + 2][n]);
        p.w = q8(tile[4 * w + 3][n]);
        ((char4*)g_ct8)[(size_t)(n0 + n) * 32 + w] = p;
    }
}

// ---------------- hybrid screening: IMMA (codes 0..95) + DP4A (codes 96..127) ----
// Grid 384 = 128 M-tiles x 3 N-thirds, 256 thr, occ 3.
// Warps 0-3: IMMA, warp tile M=32 x N=96. Warps 4-7: dp4a SIMT, 128 rows x 32 codes.
#define A_STRIDE  136
#define A_SZ      (128 * A_STRIDE)          // 17408
#define B_OFF     A_SZ
#define B_STAGE   16384
#define ICN_OFF   (B_OFF + 2 * B_STAGE)     // 50176
#define DTOP_OFF  (ICN_OFF + 1024)          // 51200
#define DTOP_SZ   (128 * 8 * 2 * 8)         // 16384
#define ENT_OFF   B_OFF                     // reused after mainloop: [128][24] Ent
#define SMEM_SZ   (DTOP_OFF + DTOP_SZ)      // 67584

struct Ent { int v; int i; };

__global__ __launch_bounds__(256, 3)
void screen_kernel() {
    extern __shared__ char smem[];
    const uint32_t sb = smem_u32(smem);
    const int tid = threadIdx.x;
    const int wid = tid >> 5, lid = tid & 31;
    const int mb = blockIdx.x / 3, nh = blockIdx.x % 3;
    const int t0  = (nh == 0) ? 0 : (nh == 1 ? 27 : 53);
    const int ntl = (nh == 0) ? 27 : 26;

    // ---- one-time: A tile (int8 rows) into padded smem + dtop init ----
    {
        const unsigned long long* xsrc =
            (const unsigned long long*)(g_x8 + (size_t)mb * 128 * EMBED_D);
        for (int t = tid; t < 2048; t += 256) {
            int row = t >> 4, c = t & 15;
            *(unsigned long long*)(smem + row * A_STRIDE + c * 8) = xsrc[t];
        }
        Ent* dt = (Ent*)(smem + DTOP_OFF);
        for (int t = tid; t < 2048; t += 256) dt[t] = Ent{0x7fffffff, 0};
    }

    // ---- IMMA thread geometry + resident A fragments ----
    const int wm = wid & 3;              // IMMA row-quarter (valid for wid<4)
    const int gr = lid >> 2, q = lid & 3;
    int a[2][4][4];
    int v[4][2], ii[4][2];
    if (wid < 4) {
        const int8_t* xb = g_x8 + (size_t)(mb * 128 + wm * 32) * EMBED_D;
#pragma unroll
        for (int g2 = 0; g2 < 2; g2++)
#pragma unroll
            for (int ks = 0; ks < 4; ks++) {
                const int8_t* r0 = xb + (g2 * 16 + gr) * EMBED_D + ks * 32 + q * 4;
                a[g2][ks][0] = *(const int*)(r0);
                a[g2][ks][1] = *(const int*)(r0 + 8 * EMBED_D);
                a[g2][ks][2] = *(const int*)(r0 + 16);
                a[g2][ks][3] = *(const int*)(r0 + 8 * EMBED_D + 16);
            }
#pragma unroll
        for (int s = 0; s < 4; s++) {
            v[s][0] = v[s][1] = 0x7fffffff;
            ii[s][0] = ii[s][1] = 0;
        }
    }

    // ---- dp4a thread geometry ----
    const int dpt = tid - 128;           // valid for wid>=4: 0..127
    const int dtx = dpt & 7, dty = dpt >> 3;

    // ---- B loader (all 256 threads) ----
    auto loadB = [&](int t, int st) {
        const int8_t* src = g_ct8 + (size_t)t * 128 * EMBED_D;
        uint32_t db = sb + B_OFF + st * B_STAGE;
#pragma unroll
        for (int i = 0; i < 4; i++) {
            int id = tid + i * 256;          // 1024 chunks
            int n = id >> 3, c = id & 7;
            cp16(db + n * 128 + (((c ^ (n & 7)) << 4)), src + n * EMBED_D + c * 16);
        }
        if (tid < 32)
            cp16(sb + ICN_OFF + st * 512 + tid * 16, g_icn + t * 128 + tid * 4);
    };

    loadB(t0, 0); cp_commit();

    for (int i = 0; i < ntl; i++) {
        if (i + 1 < ntl) { loadB(t0 + i + 1, (i + 1) & 1); cp_commit(); cp_wait<1>(); }
        else             { cp_wait<0>(); }
        __syncthreads();

        const int t = t0 + i;
        const int st = i & 1;
        const uint32_t bbase = sb + B_OFF + st * B_STAGE;
        const uint32_t cnb = sb + ICN_OFF + st * 512;

        if (wid < 4) {
            // ---------- IMMA: codes 0..95 of this tile ----------
#pragma unroll
            for (int nb = 0; nb < 12; nb++) {
                const int nloc = nb * 8;
                const uint32_t rowb = bbase + (uint32_t)(nloc + gr) * 128 + q * 4;
                int b[4][2];
#pragma unroll
                for (int ks = 0; ks < 4; ks++) {
                    b[ks][0] = lds32(rowb + ((uint32_t)((2 * ks)     ^ gr) << 4));
                    b[ks][1] = lds32(rowb + ((uint32_t)((2 * ks + 1) ^ gr) << 4));
                }
                const int2 icn = lds64(cnb + (uint32_t)(nloc + 2 * q) * 4);
                const int ng = t * 128 + nloc + 2 * q;
#pragma unroll
                for (int g2 = 0; g2 < 2; g2++) {
                    int d[4] = {0, 0, 0, 0};
#pragma unroll
                    for (int ks = 0; ks < 4; ks++)
                        mma_s8(d, a[g2][ks], b[ks][0], b[ks][1]);
                    const int slo = g2 * 2, shi = g2 * 2 + 1;
                    ins2(icn.x - d[0], ng,     v[slo], ii[slo]);
                    ins2(icn.y - d[1], ng + 1, v[slo], ii[slo]);
                    ins2(icn.x - d[2], ng,     v[shi], ii[shi]);
                    ins2(icn.y - d[3], ng + 1, v[shi], ii[shi]);
                }
            }
        } else {
            // ---------- DP4A: codes 96..127, rows {dty + 16r} ----------
            int acc[8][4];
#pragma unroll
            for (int r = 0; r < 8; r++)
#pragma unroll
                for (int j = 0; j < 4; j++) acc[r][j] = 0;

            // code n_j = 96 + j*8 + dtx  ->  n&7 == dtx (swizzle xor = dtx)
            uint32_t bj[4];
#pragma unroll
            for (int j = 0; j < 4; j++)
                bj[j] = bbase + (uint32_t)(96 + j * 8 + dtx) * 128;
            const uint32_t abase = sb + dty * A_STRIDE;

#pragma unroll 4
            for (int ip = 0; ip < 16; ip++) {       // k chunk-pairs: k = 8*ip..8*ip+7
                const uint32_t boff = (((uint32_t)((ip >> 1) ^ dtx)) << 4)
                                    + ((uint32_t)(ip & 1) << 3);
                int2 b2[4];
#pragma unroll
                for (int j = 0; j < 4; j++) b2[j] = lds64(bj[j] + boff);
#pragma unroll
                for (int r = 0; r < 8; r++) {
                    int2 a2 = lds64(abase + r * (16 * A_STRIDE) + ip * 8);
#pragma unroll
                    for (int j = 0; j < 4; j++) {
                        dp4a(acc[r][j], a2.x, b2[j].x);
                        dp4a(acc[r][j], a2.y, b2[j].y);
                    }
                }
            }

            // fold: per row best-of-4, insert into smem top-2
            int icnv[4];
#pragma unroll
            for (int j = 0; j < 4; j++)
                icnv[j] = lds32(cnb + (uint32_t)(96 + j * 8 + dtx) * 4);
#pragma unroll
            for (int r = 0; r < 8; r++) {
                const int row = dty + 16 * r;
                int bv = icnv[0] - acc[r][0];
                int bi = t * 128 + 96 + dtx;
#pragma unroll
                for (int j = 1; j < 4; j++) {
                    int s = icnv[j] - acc[r][j];
                    int n = t * 128 + 96 + j * 8 + dtx;
                    if (s < bv) { bv = s; bi = n; }
                }
                int4* slot = (int4*)(smem + DTOP_OFF + (row * 8 + dtx) * 16);
                int4 e = *slot;
                if (bv < e.z) {
                    if (bv < e.x) { e.z = e.x; e.w = e.y; e.x = bv; e.y = bi; }
                    else          { e.z = bv; e.w = bi; }
                    *slot = e;
                }
            }
        }
        __syncthreads();
    }

    // ---- merge: per row 8 IMMA entries + 16 dp4a entries -> top-4 ----
    Ent* ent = (Ent*)(smem + ENT_OFF);           // [128][24]
    if (wid < 4) {
#pragma unroll
        for (int s = 0; s < 4; s++) {
            int rloc = wm * 32 + (s >> 1) * 16 + (s & 1) * 8 + gr;
#pragma unroll
            for (int j = 0; j < 2; j++)
                ent[rloc * 24 + q * 2 + j] = Ent{v[s][j], ii[s][j]};
        }
    }
    __syncthreads();
    if (tid < 128) {
        const int row = tid;
        Ent* er = ent + row * 24;
        const Ent* dt = (const Ent*)(smem + DTOP_OFF) + row * 16;
#pragma unroll
        for (int s = 0; s < 16; s++) er[8 + s] = dt[s];
        int outb = (mb * 128 + row) * NREF + nh * NSEL;
        for (int pc = 0; pc < NSEL; pc++) {
            int bv = 0x7fffffff, bi = 0x7fffffff, bs = 0;
            for (int s = 0; s < 24; s++) {
                int ev = er[s].v, ei = er[s].i;
                if (ev < bv || (ev == bv && ei < bi)) { bv = ev; bi = ei; bs = s; }
            }
            er[bs].v = 0x7fffffff;
            g_cand[outb + pc] = bi;
        }
    }
}

// ---------------- exact fp32 refinement + fused gather / error ----------------
__global__ void refine_kernel(const float* __restrict__ X, float* __restrict__ out) {
    const int wid = threadIdx.x >> 5, lid = threadIdx.x & 31;
    const int m = blockIdx.x * 8 + wid;
    float4 xv = ((const float4*)X)[(size_t)m * 32 + lid];
    float bestv = CUDART_INF_F; int besti = 0x7fffffff;
#pragma unroll
    for (int c = 0; c < NREF; c++) {
        int j = g_cand[m * NREF + c];
        float4 cv = ((const float4*)g_ctf)[(size_t)j * 32 + lid];
        float p = xv.x * cv.x;
        p = fmaf(xv.y, cv.y, p);
        p = fmaf(xv.z, cv.z, p);
        p = fmaf(xv.w, cv.w, p);
#pragma unroll
        for (int off = 16; off > 0; off >>= 1)
            p += __shfl_xor_sync(0xFFFFFFFF, p, off);
        float s = fmaf(-2.f, p, g_cnorm[j]);
        if (s < bestv || (s == bestv && j < besti)) { bestv = s; besti = j; }
    }
    float4 cv = ((const float4*)g_ctf)[(size_t)besti * 32 + lid];
    ((float4*)out)[(size_t)m * 32 + lid] = cv;
    float dx = cv.x - xv.x, dy = cv.y - xv.y, dz = cv.z - xv.z, dw = cv.w - xv.w;
    float e = dx * dx + dy * dy + dz * dz + dw * dw;
#pragma unroll
    for (int off = 16; off > 0; off >>= 1)
        e += __shfl_xor_sync(0xFFFFFFFF, e, off);
    if (lid == 0) g_partial[m] = e;
}

// ---------------- deterministic loss reduction ----------------
__global__ void loss_kernel(float* __restrict__ out, int out_size) {
    __shared__ float sbuf[1024];
    int t = threadIdx.x;
    float s = 0.f;
    for (int i = 0; i < NSAMP / 1024; i++) s += g_partial[t + i * 1024];
    sbuf[t] = s;
    __syncthreads();
    for (int k = 512; k > 0; k >>= 1) {
        if (t < k) sbuf[t] += sbuf[t + k];
        __syncthreads();
    }
    if (t == 0)
        out[out_size - 1] = sbuf[0] * (1.25f / (float)((size_t)NSAMP * EMBED_D));
}

// ---------------- launch ----------------
extern "C" void kernel_launch(void* const* d_in, const int* in_sizes, int n_in,
                              void* d_out, int out_size) {
    const float* X  = (const float*)d_in[0];
    const float* CM = (const float*)d_in[1];
    if (n_in >= 2 && in_sizes[0] == EMBED_D * N_EMBED &&
        in_sizes[1] == NSAMP * EMBED_D) {
        const float* t = X; X = CM; CM = t;
    }
    float* out = (float*)d_out;

    cudaFuncSetAttribute(screen_kernel,
                         cudaFuncAttributeMaxDynamicSharedMemorySize, SMEM_SZ);

    split_x_kernel<<<NSAMP * EMBED_D / 4 / 256, 256>>>(X);
    split_c_kernel<<<NP2 / 64, 128>>>(CM);
    screen_kernel<<<384, 256, SMEM_SZ>>>();
    refine_kernel<<<NSAMP / 8, 256>>>(X, out);
    loss_kernel<<<1, 1024>>>(out, out_size);
}

// round 13
// speedup vs baseline: 2.9392x; 1.0265x over previous
#include <cuda_runtime.h>
#include <math_constants.h>
#include <cstdint>

// ---------------- problem constants ----------------
#define EMBED_D   128
#define N_EMBED   10000
#define NP2       10112          // 79 * 128
#define NSAMP     16384
#define NSEL      4              // candidates kept per (row, N-third)
#define NREF      12             // 3 thirds * NSEL
#define SQ        32.0f          // int8 quant scale
#define ICN_SC    512.0f         // = SQ*SQ/2 : score_int = icn - d
#define NDP       48             // codes handled by dp4a side (80..127)
#define NIM       80             // codes handled by IMMA side (0..79)

// ---------------- device scratch (no cudaMalloc allowed) ----------------
__device__ __align__(16) int8_t g_x8[NSAMP * EMBED_D];    // int8 X
__device__ __align__(16) int8_t g_ct8[NP2 * EMBED_D];     // int8 C^T, n-major
__device__ __align__(16) float  g_ctf[NP2 * EMBED_D];     // fp32 C^T, n-major (exact)
__device__ __align__(16) float  g_cnorm[NP2];             // exact fp32 norms
__device__ __align__(16) int    g_icn[NP2];               // round(512*norm), pad=1<<30
__device__ int   g_cand[NSAMP * NREF];
__device__ float g_partial[NSAMP];

// ---------------- generic-PTX helpers (plain sm_103 safe) ----------------
__device__ __forceinline__ uint32_t smem_u32(const void* p) {
    uint32_t a;
    asm("{ .reg .u64 t; cvta.to.shared.u64 t, %1; cvt.u32.u64 %0, t; }" : "=r"(a) : "l"(p));
    return a;
}
__device__ __forceinline__ void cp16(uint32_t dst, const void* src) {
    asm volatile("cp.async.cg.shared.global [%0], [%1], 16;" :: "r"(dst), "l"(src));
}
__device__ __forceinline__ void cp_commit() {
    asm volatile("cp.async.commit_group;" ::: "memory");
}
template <int N>
__device__ __forceinline__ void cp_wait() {
    asm volatile("cp.async.wait_group %0;" :: "n"(N) : "memory");
}
__device__ __forceinline__ int lds32(uint32_t addr) {
    int v;
    asm volatile("ld.shared.b32 %0, [%1];" : "=r"(v) : "r"(addr));
    return v;
}
__device__ __forceinline__ int2 lds64(uint32_t addr) {
    int2 v;
    asm volatile("ld.shared.v2.b32 {%0,%1}, [%2];" : "=r"(v.x), "=r"(v.y) : "r"(addr));
    return v;
}
__device__ __forceinline__ void mma_s8(int* d, const int* a, int b0, int b1) {
    asm volatile(
        "mma.sync.aligned.m16n8k32.row.col.s32.s8.s8.s32 "
        "{%0,%1,%2,%3}, {%4,%5,%6,%7}, {%8,%9}, {%0,%1,%2,%3};"
        : "+r"(d[0]), "+r"(d[1]), "+r"(d[2]), "+r"(d[3])
        : "r"(a[0]), "r"(a[1]), "r"(a[2]), "r"(a[3]), "r"(b0), "r"(b1));
}
__device__ __forceinline__ void dp4a(int& acc, int a, int b) {
    asm volatile("dp4a.s32.s32 %0, %1, %2, %0;" : "+r"(acc) : "r"(a), "r"(b));
}
__device__ __forceinline__ int8_t q8(float v) {
    int i = __float2int_rn(v * SQ);
    i = max(-127, min(127, i));
    return (int8_t)i;
}

// top-2 insert, integer scores (outer test rarely true)
__device__ __forceinline__ void ins2(int s, int n, int (&v)[2], int (&ii)[2]) {
    if (s < v[1]) {
        if (s < v[0]) { v[1] = v[0]; ii[1] = ii[0]; v[0] = s; ii[0] = n; }
        else          { v[1] = s; ii[1] = n; }
    }
}

// ---------------- precompute: (a) transpose C -> int8/fp32/norms, (b) int8 X ----
__global__ void prep_kernel(const float* __restrict__ X, const float* __restrict__ CM) {
    const int tid = threadIdx.x;         // 128 threads
    if (blockIdx.x < NP2 / 64) {
        __shared__ float tile[EMBED_D][65];   // 64 codes per block
        int n0 = blockIdx.x * 64;
        for (int idx = tid; idx < EMBED_D * 64; idx += 128) {
            int k = idx >> 6, n = idx & 63;
            int gn = n0 + n;
            tile[k][n] = (gn < N_EMBED) ? CM[(size_t)k * N_EMBED + gn] : 0.f;
        }
        __syncthreads();
        if (tid < 64) {
            int gn = n0 + tid;
            float s = 0.f;
#pragma unroll 8
            for (int k = 0; k < EMBED_D; k++) {
                float v = tile[k][tid];
                s = fmaf(v, v, s);
            }
            if (gn < N_EMBED) {
                g_cnorm[gn] = s;
                g_icn[gn] = __float2int_rn(s * ICN_SC);
            } else {
                g_cnorm[gn] = CUDART_INF_F;
                g_icn[gn] = 1 << 30;
            }
        }
        for (int idx = tid; idx < 64 * EMBED_D; idx += 128) {
            int n = idx >> 7, k = idx & 127;
            g_ctf[(size_t)(n0 + n) * EMBED_D + k] = tile[k][n];
        }
        for (int idx = tid; idx < 64 * 32; idx += 128) {
            int n = idx >> 5, w = idx & 31;
            char4 p;
            p.x = q8(tile[4 * w + 0][n]);
            p.y = q8(tile[4 * w + 1][n]);
            p.z = q8(tile[4 * w + 2][n]);
            p.w = q8(tile[4 * w + 3][n]);
            ((char4*)g_ct8)[(size_t)(n0 + n) * 32 + w] = p;
        }
    } else {
        // X quantize: 1024 blocks x 128 thr x 4 float4
        int b = blockIdx.x - NP2 / 64;
#pragma unroll
        for (int r = 0; r < 4; r++) {
            int i = (b * 4 + r) * 128 + tid;     // float4 index
            float4 v = ((const float4*)X)[i];
            char4 p;
            p.x = q8(v.x); p.y = q8(v.y); p.z = q8(v.z); p.w = q8(v.w);
            ((char4*)g_x8)[i] = p;
        }
    }
}

// ---------------- hybrid screening: IMMA (codes 0..79) + DP4A (codes 80..127) ----
// Grid 384 = 128 M-tiles x 3 N-thirds, 256 thr, occ 3.
// Warps 0-3: IMMA, warp tile M=32 x N=80. Warps 4-7: dp4a SIMT, 128 rows x 48 codes.
#define A_STRIDE  136
#define A_SZ      (128 * A_STRIDE)          // 17408
#define B_OFF     A_SZ
#define B_STAGE   16384
#define ICN_OFF   (B_OFF + 2 * B_STAGE)     // 50176
#define DTOP_OFF  (ICN_OFF + 1024)          // 51200
#define DTOP_SZ   (128 * 8 * 2 * 8)         // 16384
#define ENT_OFF   B_OFF                     // reused after mainloop: [128][24] Ent
#define SMEM_SZ   (DTOP_OFF + DTOP_SZ)      // 67584

struct Ent { int v; int i; };

__global__ __launch_bounds__(256, 3)
void screen_kernel() {
    extern __shared__ char smem[];
    const uint32_t sb = smem_u32(smem);
    const int tid = threadIdx.x;
    const int wid = tid >> 5, lid = tid & 31;
    const int mb = blockIdx.x / 3, nh = blockIdx.x % 3;
    const int t0  = (nh == 0) ? 0 : (nh == 1 ? 27 : 53);
    const int ntl = (nh == 0) ? 27 : 26;

    // ---- one-time: A tile (int8 rows) into padded smem + dtop init ----
    {
        const unsigned long long* xsrc =
            (const unsigned long long*)(g_x8 + (size_t)mb * 128 * EMBED_D);
        for (int t = tid; t < 2048; t += 256) {
            int row = t >> 4, c = t & 15;
            *(unsigned long long*)(smem + row * A_STRIDE + c * 8) = xsrc[t];
        }
        Ent* dt = (Ent*)(smem + DTOP_OFF);
        for (int t = tid; t < 2048; t += 256) dt[t] = Ent{0x7fffffff, 0};
    }

    // ---- IMMA thread geometry + resident A fragments ----
    const int wm = wid & 3;              // IMMA row-quarter (valid for wid<4)
    const int gr = lid >> 2, q = lid & 3;
    int a[2][4][4];
    int v[4][2], ii[4][2];
    if (wid < 4) {
        const int8_t* xb = g_x8 + (size_t)(mb * 128 + wm * 32) * EMBED_D;
#pragma unroll
        for (int g2 = 0; g2 < 2; g2++)
#pragma unroll
            for (int ks = 0; ks < 4; ks++) {
                const int8_t* r0 = xb + (g2 * 16 + gr) * EMBED_D + ks * 32 + q * 4;
                a[g2][ks][0] = *(const int*)(r0);
                a[g2][ks][1] = *(const int*)(r0 + 8 * EMBED_D);
                a[g2][ks][2] = *(const int*)(r0 + 16);
                a[g2][ks][3] = *(const int*)(r0 + 8 * EMBED_D + 16);
            }
#pragma unroll
        for (int s = 0; s < 4; s++) {
            v[s][0] = v[s][1] = 0x7fffffff;
            ii[s][0] = ii[s][1] = 0;
        }
    }

    // ---- dp4a thread geometry ----
    const int dpt = tid - 128;           // valid for wid>=4: 0..127
    const int dtx = dpt & 7, dty = dpt >> 3;

    // ---- B loader (all 256 threads) ----
    auto loadB = [&](int t, int st) {
        const int8_t* src = g_ct8 + (size_t)t * 128 * EMBED_D;
        uint32_t db = sb + B_OFF + st * B_STAGE;
#pragma unroll
        for (int i = 0; i < 4; i++) {
            int id = tid + i * 256;          // 1024 chunks
            int n = id >> 3, c = id & 7;
            cp16(db + n * 128 + (((c ^ (n & 7)) << 4)), src + n * EMBED_D + c * 16);
        }
        if (tid < 32)
            cp16(sb + ICN_OFF + st * 512 + tid * 16, g_icn + t * 128 + tid * 4);
    };

    loadB(t0, 0); cp_commit();

    for (int i = 0; i < ntl; i++) {
        if (i + 1 < ntl) { loadB(t0 + i + 1, (i + 1) & 1); cp_commit(); cp_wait<1>(); }
        else             { cp_wait<0>(); }
        __syncthreads();

        const int t = t0 + i;
        const int st = i & 1;
        const uint32_t bbase = sb + B_OFF + st * B_STAGE;
        const uint32_t cnb = sb + ICN_OFF + st * 512;

        if (wid < 4) {
            // ---------- IMMA: codes 0..79 of this tile ----------
#pragma unroll
            for (int nb = 0; nb < 10; nb++) {
                const int nloc = nb * 8;
                const uint32_t rowb = bbase + (uint32_t)(nloc + gr) * 128 + q * 4;
                int b[4][2];
#pragma unroll
                for (int ks = 0; ks < 4; ks++) {
                    b[ks][0] = lds32(rowb + ((uint32_t)((2 * ks)     ^ gr) << 4));
                    b[ks][1] = lds32(rowb + ((uint32_t)((2 * ks + 1) ^ gr) << 4));
                }
                const int2 icn = lds64(cnb + (uint32_t)(nloc + 2 * q) * 4);
                const int ng = t * 128 + nloc + 2 * q;
#pragma unroll
                for (int g2 = 0; g2 < 2; g2++) {
                    int d[4] = {0, 0, 0, 0};
#pragma unroll
                    for (int ks = 0; ks < 4; ks++)
                        mma_s8(d, a[g2][ks], b[ks][0], b[ks][1]);
                    const int slo = g2 * 2, shi = g2 * 2 + 1;
                    ins2(icn.x - d[0], ng,     v[slo], ii[slo]);
                    ins2(icn.y - d[1], ng + 1, v[slo], ii[slo]);
                    ins2(icn.x - d[2], ng,     v[shi], ii[shi]);
                    ins2(icn.y - d[3], ng + 1, v[shi], ii[shi]);
                }
            }
        } else {
            // ---------- DP4A: codes 80..127 (6 per dtx lane), rows {dty + 16r} ----------
            int acc[8][6];
#pragma unroll
            for (int r = 0; r < 8; r++)
#pragma unroll
                for (int j = 0; j < 6; j++) acc[r][j] = 0;

            // code n_j = 80 + j*8 + dtx  ->  n&7 == dtx (swizzle xor = dtx)
            const uint32_t bj0 = bbase + (uint32_t)(80 + dtx) * 128;
            const uint32_t abase = sb + dty * A_STRIDE;

#pragma unroll 4
            for (int ip = 0; ip < 16; ip++) {       // k chunk-halves: bytes ip*8..ip*8+7
                const uint32_t boff = (((uint32_t)((ip >> 1) ^ dtx)) << 4)
                                    + ((uint32_t)(ip & 1) << 3);
                int2 b2[6];
#pragma unroll
                for (int j = 0; j < 6; j++) b2[j] = lds64(bj0 + (uint32_t)(j * 8) * 128 + boff);
#pragma unroll
                for (int r = 0; r < 8; r++) {
                    int2 a2 = lds64(abase + r * (16 * A_STRIDE) + ip * 8);
#pragma unroll
                    for (int j = 0; j < 6; j++) {
                        dp4a(acc[r][j], a2.x, b2[j].x);
                        dp4a(acc[r][j], a2.y, b2[j].y);
                    }
                }
            }

            // fold: per row best-of-6, insert into smem top-2
            int icnv[6];
#pragma unroll
            for (int j = 0; j < 6; j++)
                icnv[j] = lds32(cnb + (uint32_t)(80 + j * 8 + dtx) * 4);
#pragma unroll
            for (int r = 0; r < 8; r++) {
                const int row = dty + 16 * r;
                int bv = icnv[0] - acc[r][0];
                int bi = t * 128 + 80 + dtx;
#pragma unroll
                for (int j = 1; j < 6; j++) {
                    int s = icnv[j] - acc[r][j];
                    int n = t * 128 + 80 + j * 8 + dtx;
                    if (s < bv) { bv = s; bi = n; }
                }
                int4* slot = (int4*)(smem + DTOP_OFF + (row * 8 + dtx) * 16);
                int4 e = *slot;
                if (bv < e.z) {
                    if (bv < e.x) { e.z = e.x; e.w = e.y; e.x = bv; e.y = bi; }
                    else          { e.z = bv; e.w = bi; }
                    *slot = e;
                }
            }
        }
        __syncthreads();
    }

    // ---- merge: per row 8 IMMA entries + 16 dp4a entries -> top-4 ----
    Ent* ent = (Ent*)(smem + ENT_OFF);           // [128][24]
    if (wid < 4) {
#pragma unroll
        for (int s = 0; s < 4; s++) {
            int rloc = wm * 32 + (s >> 1) * 16 + (s & 1) * 8 + gr;
#pragma unroll
            for (int j = 0; j < 2; j++)
                ent[rloc * 24 + q * 2 + j] = Ent{v[s][j], ii[s][j]};
        }
    }
    __syncthreads();
    if (tid < 128) {
        const int row = tid;
        Ent* er = ent + row * 24;
        const Ent* dt = (const Ent*)(smem + DTOP_OFF) + row * 16;
#pragma unroll
        for (int s = 0; s < 16; s++) er[8 + s] = dt[s];
        int outb = (mb * 128 + row) * NREF + nh * NSEL;
        for (int pc = 0; pc < NSEL; pc++) {
            int bv = 0x7fffffff, bi = 0x7fffffff, bs = 0;
            for (int s = 0; s < 24; s++) {
                int ev = er[s].v, ei = er[s].i;
                if (ev < bv || (ev == bv && ei < bi)) { bv = ev; bi = ei; bs = s; }
            }
            er[bs].v = 0x7fffffff;
            g_cand[outb + pc] = bi;
        }
    }
}

// ---------------- exact fp32 refinement + fused gather / error ----------------
__global__ void refine_kernel(const float* __restrict__ X, float* __restrict__ out) {
    const int wid = threadIdx.x >> 5, lid = threadIdx.x & 31;
    const int m = blockIdx.x * 8 + wid;
    float4 xv = ((const float4*)X)[(size_t)m * 32 + lid];
    float bestv = CUDART_INF_F; int besti = 0x7fffffff;
#pragma unroll
    for (int c = 0; c < NREF; c++) {
        int j = g_cand[m * NREF + c];
        float4 cv = ((const float4*)g_ctf)[(size_t)j * 32 + lid];
        float p = xv.x * cv.x;
        p = fmaf(xv.y, cv.y, p);
        p = fmaf(xv.z, cv.z, p);
        p = fmaf(xv.w, cv.w, p);
#pragma unroll
        for (int off = 16; off > 0; off >>= 1)
            p += __shfl_xor_sync(0xFFFFFFFF, p, off);
        float s = fmaf(-2.f, p, g_cnorm[j]);
        if (s < bestv || (s == bestv && j < besti)) { bestv = s; besti = j; }
    }
    float4 cv = ((const float4*)g_ctf)[(size_t)besti * 32 + lid];
    ((float4*)out)[(size_t)m * 32 + lid] = cv;
    float dx = cv.x - xv.x, dy = cv.y - xv.y, dz = cv.z - xv.z, dw = cv.w - xv.w;
    float e = dx * dx + dy * dy + dz * dz + dw * dw;
#pragma unroll
    for (int off = 16; off > 0; off >>= 1)
        e += __shfl_xor_sync(0xFFFFFFFF, e, off);
    if (lid == 0) g_partial[m] = e;
}

// ---------------- deterministic loss reduction ----------------
__global__ void loss_kernel(float* __restrict__ out, int out_size) {
    __shared__ float sbuf[1024];
    int t = threadIdx.x;
    float s = 0.f;
    for (int i = 0; i < NSAMP / 1024; i++) s += g_partial[t + i * 1024];
    sbuf[t] = s;
    __syncthreads();
    for (int k = 512; k > 0; k >>= 1) {
        if (t < k) sbuf[t] += sbuf[t + k];
        __syncthreads();
    }
    if (t == 0)
        out[out_size - 1] = sbuf[0] * (1.25f / (float)((size_t)NSAMP * EMBED_D));
}

// ---------------- launch ----------------
extern "C" void kernel_launch(void* const* d_in, const int* in_sizes, int n_in,
                              void* d_out, int out_size) {
    const float* X  = (const float*)d_in[0];
    const float* CM = (const float*)d_in[1];
    if (n_in >= 2 && in_sizes[0] == EMBED_D * N_EMBED &&
        in_sizes[1] == NSAMP * EMBED_D) {
        const float* t = X; X = CM; CM = t;
    }
    float* out = (float*)d_out;

    cudaFuncSetAttribute(screen_kernel,
                         cudaFuncAttributeMaxDynamicSharedMemorySize, SMEM_SZ);

    prep_kernel<<<NP2 / 64 + NSAMP * EMBED_D / 4 / 512, 128>>>(X, CM);
    screen_kernel<<<384, 256, SMEM_SZ>>>();
    refine_kernel<<<NSAMP / 8, 256>>>(X, out);
    loss_kernel<<<1, 1024>>>(out, out_size);
}

// round 14
// speedup vs baseline: 2.9801x; 1.0139x over previous
#include <cuda_runtime.h>
#include <math_constants.h>
#include <cstdint>

// ---------------- problem constants ----------------
#define EMBED_D   128
#define N_EMBED   10000
#define NP2       10112          // 79 * 128
#define NSAMP     16384
#define NSEL      4              // candidates kept per (row, N-third)
#define NREF      12             // 3 thirds * NSEL
#define SQ        32.0f          // int8 quant scale
#define ICN_SC    512.0f         // = SQ*SQ/2 : score_int = icn - d
#define NIM       88             // codes on IMMA side (0..87)
#define NDP       40             // codes on dp4a side (88..127), 5 per dtx lane

// ---------------- device scratch (no cudaMalloc allowed) ----------------
__device__ __align__(16) int8_t g_x8[NSAMP * EMBED_D];    // int8 X
__device__ __align__(16) int8_t g_ct8[NP2 * EMBED_D];     // int8 C^T, n-major
__device__ __align__(16) float  g_ctf[NP2 * EMBED_D];     // fp32 C^T, n-major (exact)
__device__ __align__(16) float  g_cnorm[NP2];             // exact fp32 norms
__device__ __align__(16) int    g_icn[NP2];               // round(512*norm), pad=1<<30
__device__ int   g_cand[NSAMP * NREF];
__device__ float g_partial[NSAMP];

// ---------------- generic-PTX helpers (plain sm_103 safe) ----------------
__device__ __forceinline__ uint32_t smem_u32(const void* p) {
    uint32_t a;
    asm("{ .reg .u64 t; cvta.to.shared.u64 t, %1; cvt.u32.u64 %0, t; }" : "=r"(a) : "l"(p));
    return a;
}
__device__ __forceinline__ void cp16(uint32_t dst, const void* src) {
    asm volatile("cp.async.cg.shared.global [%0], [%1], 16;" :: "r"(dst), "l"(src));
}
__device__ __forceinline__ void cp_commit() {
    asm volatile("cp.async.commit_group;" ::: "memory");
}
template <int N>
__device__ __forceinline__ void cp_wait() {
    asm volatile("cp.async.wait_group %0;" :: "n"(N) : "memory");
}
__device__ __forceinline__ int lds32(uint32_t addr) {
    int v;
    asm volatile("ld.shared.b32 %0, [%1];" : "=r"(v) : "r"(addr));
    return v;
}
__device__ __forceinline__ int2 lds64(uint32_t addr) {
    int2 v;
    asm volatile("ld.shared.v2.b32 {%0,%1}, [%2];" : "=r"(v.x), "=r"(v.y) : "r"(addr));
    return v;
}
__device__ __forceinline__ void mma_s8(int* d, const int* a, int b0, int b1) {
    asm volatile(
        "mma.sync.aligned.m16n8k32.row.col.s32.s8.s8.s32 "
        "{%0,%1,%2,%3}, {%4,%5,%6,%7}, {%8,%9}, {%0,%1,%2,%3};"
        : "+r"(d[0]), "+r"(d[1]), "+r"(d[2]), "+r"(d[3])
        : "r"(a[0]), "r"(a[1]), "r"(a[2]), "r"(a[3]), "r"(b0), "r"(b1));
}
__device__ __forceinline__ void dp4a(int& acc, int a, int b) {
    asm volatile("dp4a.s32.s32 %0, %1, %2, %0;" : "+r"(acc) : "r"(a), "r"(b));
}
__device__ __forceinline__ int8_t q8(float v) {
    int i = __float2int_rn(v * SQ);
    i = max(-127, min(127, i));
    return (int8_t)i;
}

// top-2 insert, integer scores (outer test rarely true)
__device__ __forceinline__ void ins2(int s, int n, int (&v)[2], int (&ii)[2]) {
    if (s < v[1]) {
        if (s < v[0]) { v[1] = v[0]; ii[1] = ii[0]; v[0] = s; ii[0] = n; }
        else          { v[1] = s; ii[1] = n; }
    }
}

// ---------------- precompute: (a) transpose C -> int8/fp32/norms, (b) int8 X ----
__global__ void prep_kernel(const float* __restrict__ X, const float* __restrict__ CM) {
    const int tid = threadIdx.x;         // 128 threads
    if (blockIdx.x < NP2 / 64) {
        __shared__ float tile[EMBED_D][65];   // 64 codes per block
        int n0 = blockIdx.x * 64;
        for (int idx = tid; idx < EMBED_D * 64; idx += 128) {
            int k = idx >> 6, n = idx & 63;
            int gn = n0 + n;
            tile[k][n] = (gn < N_EMBED) ? CM[(size_t)k * N_EMBED + gn] : 0.f;
        }
        __syncthreads();
        if (tid < 64) {
            int gn = n0 + tid;
            float s = 0.f;
#pragma unroll 8
            for (int k = 0; k < EMBED_D; k++) {
                float v = tile[k][tid];
                s = fmaf(v, v, s);
            }
            if (gn < N_EMBED) {
                g_cnorm[gn] = s;
                g_icn[gn] = __float2int_rn(s * ICN_SC);
            } else {
                g_cnorm[gn] = CUDART_INF_F;
                g_icn[gn] = 1 << 30;
            }
        }
        for (int idx = tid; idx < 64 * EMBED_D; idx += 128) {
            int n = idx >> 7, k = idx & 127;
            g_ctf[(size_t)(n0 + n) * EMBED_D + k] = tile[k][n];
        }
        for (int idx = tid; idx < 64 * 32; idx += 128) {
            int n = idx >> 5, w = idx & 31;
            char4 p;
            p.x = q8(tile[4 * w + 0][n]);
            p.y = q8(tile[4 * w + 1][n]);
            p.z = q8(tile[4 * w + 2][n]);
            p.w = q8(tile[4 * w + 3][n]);
            ((char4*)g_ct8)[(size_t)(n0 + n) * 32 + w] = p;
        }
    } else {
        // X quantize: 1024 virtual blocks x 128 thr x 4 float4
        int b = blockIdx.x - NP2 / 64;
#pragma unroll
        for (int r = 0; r < 4; r++) {
            int i = (b * 4 + r) * 128 + tid;     // float4 index
            float4 v = ((const float4*)X)[i];
            char4 p;
            p.x = q8(v.x); p.y = q8(v.y); p.z = q8(v.z); p.w = q8(v.w);
            ((char4*)g_x8)[i] = p;
        }
    }
}

// ---------------- hybrid screening: IMMA (codes 0..87) + DP4A (codes 88..127) ----
// Grid 384 = 128 M-tiles x 3 N-thirds, 256 thr, occ 3.
// Warps 0-3: IMMA, warp tile M=32 x N=88. Warps 4-7: dp4a SIMT, 128 rows x 40 codes.
#define A_STRIDE  136
#define A_SZ      (128 * A_STRIDE)          // 17408
#define B_OFF     A_SZ
#define B_STAGE   16384
#define ICN_OFF   (B_OFF + 2 * B_STAGE)     // 50176
#define DTOP_OFF  (ICN_OFF + 1024)          // 51200
#define DTOP_SZ   (128 * 8 * 2 * 8)         // 16384
#define ENT_OFF   B_OFF                     // reused after mainloop: [128][24] Ent
#define SMEM_SZ   (DTOP_OFF + DTOP_SZ)      // 67584

struct Ent { int v; int i; };

__global__ __launch_bounds__(256, 3)
void screen_kernel() {
    extern __shared__ char smem[];
    const uint32_t sb = smem_u32(smem);
    const int tid = threadIdx.x;
    const int wid = tid >> 5, lid = tid & 31;
    const int mb = blockIdx.x / 3, nh = blockIdx.x % 3;
    const int t0  = (nh == 0) ? 0 : (nh == 1 ? 27 : 53);
    const int ntl = (nh == 0) ? 27 : 26;

    // ---- one-time: A tile (int8 rows) into padded smem + dtop init ----
    {
        const unsigned long long* xsrc =
            (const unsigned long long*)(g_x8 + (size_t)mb * 128 * EMBED_D);
        for (int t = tid; t < 2048; t += 256) {
            int row = t >> 4, c = t & 15;
            *(unsigned long long*)(smem + row * A_STRIDE + c * 8) = xsrc[t];
        }
        Ent* dt = (Ent*)(smem + DTOP_OFF);
        for (int t = tid; t < 2048; t += 256) dt[t] = Ent{0x7fffffff, 0};
    }

    // ---- IMMA thread geometry + resident A fragments ----
    const int wm = wid & 3;              // IMMA row-quarter (valid for wid<4)
    const int gr = lid >> 2, q = lid & 3;
    int a[2][4][4];
    int v[4][2], ii[4][2];
    if (wid < 4) {
        const int8_t* xb = g_x8 + (size_t)(mb * 128 + wm * 32) * EMBED_D;
#pragma unroll
        for (int g2 = 0; g2 < 2; g2++)
#pragma unroll
            for (int ks = 0; ks < 4; ks++) {
                const int8_t* r0 = xb + (g2 * 16 + gr) * EMBED_D + ks * 32 + q * 4;
                a[g2][ks][0] = *(const int*)(r0);
                a[g2][ks][1] = *(const int*)(r0 + 8 * EMBED_D);
                a[g2][ks][2] = *(const int*)(r0 + 16);
                a[g2][ks][3] = *(const int*)(r0 + 8 * EMBED_D + 16);
            }
#pragma unroll
        for (int s = 0; s < 4; s++) {
            v[s][0] = v[s][1] = 0x7fffffff;
            ii[s][0] = ii[s][1] = 0;
        }
    }

    // ---- dp4a thread geometry ----
    const int dpt = tid - 128;           // valid for wid>=4: 0..127
    const int dtx = dpt & 7, dty = dpt >> 3;

    // ---- B loader (all 256 threads) ----
    auto loadB = [&](int t, int st) {
        const int8_t* src = g_ct8 + (size_t)t * 128 * EMBED_D;
        uint32_t db = sb + B_OFF + st * B_STAGE;
#pragma unroll
        for (int i = 0; i < 4; i++) {
            int id = tid + i * 256;          // 1024 chunks
            int n = id >> 3, c = id & 7;
            cp16(db + n * 128 + (((c ^ (n & 7)) << 4)), src + n * EMBED_D + c * 16);
        }
        if (tid < 32)
            cp16(sb + ICN_OFF + st * 512 + tid * 16, g_icn + t * 128 + tid * 4);
    };

    loadB(t0, 0); cp_commit();

    for (int i = 0; i < ntl; i++) {
        if (i + 1 < ntl) { loadB(t0 + i + 1, (i + 1) & 1); cp_commit(); cp_wait<1>(); }
        else             { cp_wait<0>(); }
        __syncthreads();

        const int t = t0 + i;
        const int st = i & 1;
        const uint32_t bbase = sb + B_OFF + st * B_STAGE;
        const uint32_t cnb = sb + ICN_OFF + st * 512;

        if (wid < 4) {
            // ---------- IMMA: codes 0..87 of this tile ----------
#pragma unroll
            for (int nb = 0; nb < 11; nb++) {
                const int nloc = nb * 8;
                const uint32_t rowb = bbase + (uint32_t)(nloc + gr) * 128 + q * 4;
                int b[4][2];
#pragma unroll
                for (int ks = 0; ks < 4; ks++) {
                    b[ks][0] = lds32(rowb + ((uint32_t)((2 * ks)     ^ gr) << 4));
                    b[ks][1] = lds32(rowb + ((uint32_t)((2 * ks + 1) ^ gr) << 4));
                }
                const int2 icn = lds64(cnb + (uint32_t)(nloc + 2 * q) * 4);
                const int ng = t * 128 + nloc + 2 * q;
#pragma unroll
                for (int g2 = 0; g2 < 2; g2++) {
                    int d[4] = {0, 0, 0, 0};
#pragma unroll
                    for (int ks = 0; ks < 4; ks++)
                        mma_s8(d, a[g2][ks], b[ks][0], b[ks][1]);
                    const int slo = g2 * 2, shi = g2 * 2 + 1;
                    ins2(icn.x - d[0], ng,     v[slo], ii[slo]);
                    ins2(icn.y - d[1], ng + 1, v[slo], ii[slo]);
                    ins2(icn.x - d[2], ng,     v[shi], ii[shi]);
                    ins2(icn.y - d[3], ng + 1, v[shi], ii[shi]);
                }
            }
        } else {
            // ---------- DP4A: codes 88..127 (5 per dtx lane), rows {dty + 16r} ----------
            int acc[8][5];
#pragma unroll
            for (int r = 0; r < 8; r++)
#pragma unroll
                for (int j = 0; j < 5; j++) acc[r][j] = 0;

            // code n_j = 88 + j*8 + dtx  ->  n&7 == dtx (swizzle xor = dtx)
            const uint32_t bj0 = bbase + (uint32_t)(88 + dtx) * 128;
            const uint32_t abase = sb + dty * A_STRIDE;

#pragma unroll 4
            for (int ip = 0; ip < 16; ip++) {       // k chunk-halves: bytes ip*8..ip*8+7
                const uint32_t boff = (((uint32_t)((ip >> 1) ^ dtx)) << 4)
                                    + ((uint32_t)(ip & 1) << 3);
                int2 b2[5];
#pragma unroll
                for (int j = 0; j < 5; j++) b2[j] = lds64(bj0 + (uint32_t)(j * 8) * 128 + boff);
#pragma unroll
                for (int r = 0; r < 8; r++) {
                    int2 a2 = lds64(abase + r * (16 * A_STRIDE) + ip * 8);
#pragma unroll
                    for (int j = 0; j < 5; j++) {
                        dp4a(acc[r][j], a2.x, b2[j].x);
                        dp4a(acc[r][j], a2.y, b2[j].y);
                    }
                }
            }

            // fold: per row best-of-5, insert into smem top-2
            int icnv[5];
#pragma unroll
            for (int j = 0; j < 5; j++)
                icnv[j] = lds32(cnb + (uint32_t)(88 + j * 8 + dtx) * 4);
#pragma unroll
            for (int r = 0; r < 8; r++) {
                const int row = dty + 16 * r;
                int bv = icnv[0] - acc[r][0];
                int bi = t * 128 + 88 + dtx;
#pragma unroll
                for (int j = 1; j < 5; j++) {
                    int s = icnv[j] - acc[r][j];
                    int n = t * 128 + 88 + j * 8 + dtx;
                    if (s < bv) { bv = s; bi = n; }
                }
                int4* slot = (int4*)(smem + DTOP_OFF + (row * 8 + dtx) * 16);
                int4 e = *slot;
                if (bv < e.z) {
                    if (bv < e.x) { e.z = e.x; e.w = e.y; e.x = bv; e.y = bi; }
                    else          { e.z = bv; e.w = bi; }
                    *slot = e;
                }
            }
        }
        __syncthreads();
    }

    // ---- merge: per row 8 IMMA entries + 16 dp4a entries -> top-4 ----
    Ent* ent = (Ent*)(smem + ENT_OFF);           // [128][24]
    if (wid < 4) {
#pragma unroll
        for (int s = 0; s < 4; s++) {
            int rloc = wm * 32 + (s >> 1) * 16 + (s & 1) * 8 + gr;
#pragma unroll
            for (int j = 0; j < 2; j++)
                ent[rloc * 24 + q * 2 + j] = Ent{v[s][j], ii[s][j]};
        }
    }
    __syncthreads();
    if (tid < 128) {
        const int row = tid;
        Ent* er = ent + row * 24;
        const Ent* dt = (const Ent*)(smem + DTOP_OFF) + row * 16;
#pragma unroll
        for (int s = 0; s < 16; s++) er[8 + s] = dt[s];
        int outb = (mb * 128 + row) * NREF + nh * NSEL;
        for (int pc = 0; pc < NSEL; pc++) {
            int bv = 0x7fffffff, bi = 0x7fffffff, bs = 0;
            for (int s = 0; s < 24; s++) {
                int ev = er[s].v, ei = er[s].i;
                if (ev < bv || (ev == bv && ei < bi)) { bv = ev; bi = ei; bs = s; }
            }
            er[bs].v = 0x7fffffff;
            g_cand[outb + pc] = bi;
        }
    }
}

// ---------------- exact fp32 refinement + fused gather / error ----------------
__global__ void refine_kernel(const float* __restrict__ X, float* __restrict__ out) {
    const int wid = threadIdx.x >> 5, lid = threadIdx.x & 31;
    const int m = blockIdx.x * 8 + wid;
    float4 xv = ((const float4*)X)[(size_t)m * 32 + lid];
    float bestv = CUDART_INF_F; int besti = 0x7fffffff;
#pragma unroll
    for (int c = 0; c < NREF; c++) {
        int j = g_cand[m * NREF + c];
        float4 cv = ((const float4*)g_ctf)[(size_t)j * 32 + lid];
        float p = xv.x * cv.x;
        p = fmaf(xv.y, cv.y, p);
        p = fmaf(xv.z, cv.z, p);
        p = fmaf(xv.w, cv.w, p);
#pragma unroll
        for (int off = 16; off > 0; off >>= 1)
            p += __shfl_xor_sync(0xFFFFFFFF, p, off);
        float s = fmaf(-2.f, p, g_cnorm[j]);
        if (s < bestv || (s == bestv && j < besti)) { bestv = s; besti = j; }
    }
    float4 cv = ((const float4*)g_ctf)[(size_t)besti * 32 + lid];
    ((float4*)out)[(size_t)m * 32 + lid] = cv;
    float dx = cv.x - xv.x, dy = cv.y - xv.y, dz = cv.z - xv.z, dw = cv.w - xv.w;
    float e = dx * dx + dy * dy + dz * dz + dw * dw;
#pragma unroll
    for (int off = 16; off > 0; off >>= 1)
        e += __shfl_xor_sync(0xFFFFFFFF, e, off);
    if (lid == 0) g_partial[m] = e;
}

// ---------------- deterministic loss reduction ----------------
__global__ void loss_kernel(float* __restrict__ out, int out_size) {
    __shared__ float sbuf[1024];
    int t = threadIdx.x;
    float s = 0.f;
    for (int i = 0; i < NSAMP / 1024; i++) s += g_partial[t + i * 1024];
    sbuf[t] = s;
    __syncthreads();
    for (int k = 512; k > 0; k >>= 1) {
        if (t < k) sbuf[t] += sbuf[t + k];
        __syncthreads();
    }
    if (t == 0)
        out[out_size - 1] = sbuf[0] * (1.25f / (float)((size_t)NSAMP * EMBED_D));
}

// ---------------- launch ----------------
extern "C" void kernel_launch(void* const* d_in, const int* in_sizes, int n_in,
                              void* d_out, int out_size) {
    const float* X  = (const float*)d_in[0];
    const float* CM = (const float*)d_in[1];
    if (n_in >= 2 && in_sizes[0] == EMBED_D * N_EMBED &&
        in_sizes[1] == NSAMP * EMBED_D) {
        const float* t = X; X = CM; CM = t;
    }
    float* out = (float*)d_out;

    cudaFuncSetAttribute(screen_kernel,
                         cudaFuncAttributeMaxDynamicSharedMemorySize, SMEM_SZ);

    prep_kernel<<<NP2 / 64 + NSAMP * EMBED_D / 4 / 512, 128>>>(X, CM);
    screen_kernel<<<384, 256, SMEM_SZ>>>();
    refine_kernel<<<NSAMP / 8, 256>>>(X, out);
    loss_kernel<<<1, 1024>>>(out, out_size);
}

// round 15
// speedup vs baseline: 3.3362x; 1.1195x over previous
#include <cuda_runtime.h>
#include <math_constants.h>
#include <cstdint>

// ---------------- problem constants ----------------
#define EMBED_D   128
#define N_EMBED   10000
#define NP2       10112          // 79 * 128
#define NTILE     79
#define NSAMP     16384
#define TOTU      (128 * NTILE)  // 10112 fine units (M-tile, code-tile)
#define NCTA_S    444            // 148 SMs x occ 3, single wave
#define NSLOT     5              // max chunks overlapping one M-tile
#define NKEEP     3              // candidates per (row, chunk)
#define NREF      (NSLOT * NKEEP)// 15
#define SQ        32.0f          // int8 quant scale
#define ICN_SC    512.0f         // = SQ*SQ/2 : score_int = icn - d

// ---------------- device scratch (no cudaMalloc allowed) ----------------
__device__ __align__(16) int8_t g_x8[NSAMP * EMBED_D];    // int8 X
__device__ __align__(16) int8_t g_ct8[NP2 * EMBED_D];     // int8 C^T, n-major
__device__ __align__(16) float  g_ctf[NP2 * EMBED_D];     // fp32 C^T, n-major (exact)
__device__ __align__(16) float  g_cnorm[NP2];             // exact fp32 norms
__device__ __align__(16) int    g_icn[NP2];               // round(512*norm), pad=1<<30
__device__ int   g_cand[NSAMP * NREF];
__device__ float g_partial[NSAMP];

// ---------------- generic-PTX helpers (plain sm_103 safe) ----------------
__device__ __forceinline__ uint32_t smem_u32(const void* p) {
    uint32_t a;
    asm("{ .reg .u64 t; cvta.to.shared.u64 t, %1; cvt.u32.u64 %0, t; }" : "=r"(a) : "l"(p));
    return a;
}
__device__ __forceinline__ void cp16(uint32_t dst, const void* src) {
    asm volatile("cp.async.cg.shared.global [%0], [%1], 16;" :: "r"(dst), "l"(src));
}
__device__ __forceinline__ void cp_commit() {
    asm volatile("cp.async.commit_group;" ::: "memory");
}
template <int N>
__device__ __forceinline__ void cp_wait() {
    asm volatile("cp.async.wait_group %0;" :: "n"(N) : "memory");
}
__device__ __forceinline__ int lds32(uint32_t addr) {
    int v;
    asm volatile("ld.shared.b32 %0, [%1];" : "=r"(v) : "r"(addr));
    return v;
}
__device__ __forceinline__ int2 lds64(uint32_t addr) {
    int2 v;
    asm volatile("ld.shared.v2.b32 {%0,%1}, [%2];" : "=r"(v.x), "=r"(v.y) : "r"(addr));
    return v;
}
__device__ __forceinline__ void mma_s8(int* d, const int* a, int b0, int b1) {
    asm volatile(
        "mma.sync.aligned.m16n8k32.row.col.s32.s8.s8.s32 "
        "{%0,%1,%2,%3}, {%4,%5,%6,%7}, {%8,%9}, {%0,%1,%2,%3};"
        : "+r"(d[0]), "+r"(d[1]), "+r"(d[2]), "+r"(d[3])
        : "r"(a[0]), "r"(a[1]), "r"(a[2]), "r"(a[3]), "r"(b0), "r"(b1));
}
__device__ __forceinline__ void dp4a(int& acc, int a, int b) {
    asm volatile("dp4a.s32.s32 %0, %1, %2, %0;" : "+r"(acc) : "r"(a), "r"(b));
}
__device__ __forceinline__ int8_t q8(float v) {
    int i = __float2int_rn(v * SQ);
    i = max(-127, min(127, i));
    return (int8_t)i;
}

// top-2 insert, integer scores (outer test rarely true)
__device__ __forceinline__ void ins2(int s, int n, int (&v)[2], int (&ii)[2]) {
    if (s < v[1]) {
        if (s < v[0]) { v[1] = v[0]; ii[1] = ii[0]; v[0] = s; ii[0] = n; }
        else          { v[1] = s; ii[1] = n; }
    }
}

// ---------------- precompute: C transpose/norms, X int8, g_cand prefill ----------------
#define PREP_CB  (NP2 / 64)          // 158
#define PREP_XB  1024
#define PREP_ZB  (NSAMP * NREF / (128 * 16))  // 120

__global__ void prep_kernel(const float* __restrict__ X, const float* __restrict__ CM) {
    const int tid = threadIdx.x;         // 128 threads
    if (blockIdx.x < PREP_CB) {
        __shared__ float tile[EMBED_D][65];   // 64 codes per block
        int n0 = blockIdx.x * 64;
        for (int idx = tid; idx < EMBED_D * 64; idx += 128) {
            int k = idx >> 6, n = idx & 63;
            int gn = n0 + n;
            tile[k][n] = (gn < N_EMBED) ? CM[(size_t)k * N_EMBED + gn] : 0.f;
        }
        __syncthreads();
        if (tid < 64) {
            int gn = n0 + tid;
            float s = 0.f;
#pragma unroll 8
            for (int k = 0; k < EMBED_D; k++) {
                float v = tile[k][tid];
                s = fmaf(v, v, s);
            }
            if (gn < N_EMBED) {
                g_cnorm[gn] = s;
                g_icn[gn] = __float2int_rn(s * ICN_SC);
            } else {
                g_cnorm[gn] = CUDART_INF_F;
                g_icn[gn] = 1 << 30;
            }
        }
        for (int idx = tid; idx < 64 * EMBED_D; idx += 128) {
            int n = idx >> 7, k = idx & 127;
            g_ctf[(size_t)(n0 + n) * EMBED_D + k] = tile[k][n];
        }
        for (int idx = tid; idx < 64 * 32; idx += 128) {
            int n = idx >> 5, w = idx & 31;
            char4 p;
            p.x = q8(tile[4 * w + 0][n]);
            p.y = q8(tile[4 * w + 1][n]);
            p.z = q8(tile[4 * w + 2][n]);
            p.w = q8(tile[4 * w + 3][n]);
            ((char4*)g_ct8)[(size_t)(n0 + n) * 32 + w] = p;
        }
    } else if (blockIdx.x < PREP_CB + PREP_XB) {
        // X quantize: 1024 blocks x 128 thr x 4 float4
        int b = blockIdx.x - PREP_CB;
#pragma unroll
        for (int r = 0; r < 4; r++) {
            int i = (b * 4 + r) * 128 + tid;     // float4 index
            float4 v = ((const float4*)X)[i];
            char4 p;
            p.x = q8(v.x); p.y = q8(v.y); p.z = q8(v.z); p.w = q8(v.w);
            ((char4*)g_x8)[i] = p;
        }
    } else {
        // prefill g_cand with code 0 (unwritten slots harmlessly refined)
        int b = blockIdx.x - PREP_CB - PREP_XB;
        int4* dst = (int4*)g_cand + (b * 128 + tid) * 4;
#pragma unroll
        for (int k = 0; k < 4; k++) dst[k] = make_int4(0, 0, 0, 0);
    }
}

// ---------------- hybrid screening, statically balanced chunks ----------------
// Grid 444 = 148 SMs x occ 3. CTA i owns units [TOTU*i/444, TOTU*(i+1)/444).
// Unit u -> (mb = u/79, t = u%79). Warps 0-3 IMMA (codes 0..87), 4-7 dp4a (88..127).
#define A_STRIDE  136
#define A_SZ      (128 * A_STRIDE)          // 17408
#define B_OFF     A_SZ
#define B_STAGE   16384
#define ICN_OFF   (B_OFF + 2 * B_STAGE)     // 50176
#define DTOP_OFF  (ICN_OFF + 1024)          // 51200
#define DTOP_STR  192                       // 24 Ent per row
#define DTOP_SZ   (128 * DTOP_STR)          // 24576
#define SMEM_SZ   (DTOP_OFF + DTOP_SZ)      // 75776

struct Ent { int v; int i; };

__global__ __launch_bounds__(256, 3)
void screen_kernel() {
    extern __shared__ char smem[];
    const uint32_t sb = smem_u32(smem);
    const int tid = threadIdx.x;
    const int wid = tid >> 5, lid = tid & 31;
    const int cta = blockIdx.x;
    const int u0 = (int)(((long long)TOTU * cta) / NCTA_S);
    const int u1 = (int)(((long long)TOTU * (cta + 1)) / NCTA_S);

    // ---- thread geometry ----
    const int wm = wid & 3;              // IMMA row-quarter (wid<4)
    const int gr = lid >> 2, q = lid & 3;
    const int dpt = tid - 128;           // dp4a (wid>=4)
    const int dtx = dpt & 7, dty = dpt >> 3;

    int a[2][4][4];                      // IMMA resident A frags
    int v[4][2], ii[4][2];               // IMMA per-lane top-2

    // ---- B loader (all 256 threads); B depends only on tile t ----
    auto loadB = [&](int t, int st) {
        const int8_t* src = g_ct8 + (size_t)t * 128 * EMBED_D;
        uint32_t db = sb + B_OFF + st * B_STAGE;
#pragma unroll
        for (int i = 0; i < 4; i++) {
            int id = tid + i * 256;          // 1024 chunks
            int n = id >> 3, c = id & 7;
            cp16(db + n * 128 + (((c ^ (n & 7)) << 4)), src + n * EMBED_D + c * 16);
        }
        if (tid < 32)
            cp16(sb + ICN_OFF + st * 512 + tid * 16, g_icn + t * 128 + tid * 4);
    };

    // ---- per-mb setup: A smem + IMMA frags + dtop/lane-top reset ----
    auto setupMB = [&](int mb) {
        const unsigned long long* xsrc =
            (const unsigned long long*)(g_x8 + (size_t)mb * 128 * EMBED_D);
        for (int t = tid; t < 2048; t += 256) {
            int row = t >> 4, c = t & 15;
            *(unsigned long long*)(smem + row * A_STRIDE + c * 8) = xsrc[t];
        }
        int4* dt = (int4*)(smem + DTOP_OFF);
        const int4 inf4 = make_int4(0x7fffffff, 0, 0x7fffffff, 0);
        for (int t = tid; t < DTOP_SZ / 16; t += 256) dt[t] = inf4;
        if (wid < 4) {
            const int8_t* xb = g_x8 + (size_t)(mb * 128 + wm * 32) * EMBED_D;
#pragma unroll
            for (int g2 = 0; g2 < 2; g2++)
#pragma unroll
                for (int ks = 0; ks < 4; ks++) {
                    const int8_t* r0 = xb + (g2 * 16 + gr) * EMBED_D + ks * 32 + q * 4;
                    a[g2][ks][0] = *(const int*)(r0);
                    a[g2][ks][1] = *(const int*)(r0 + 8 * EMBED_D);
                    a[g2][ks][2] = *(const int*)(r0 + 16);
                    a[g2][ks][3] = *(const int*)(r0 + 8 * EMBED_D + 16);
                }
#pragma unroll
            for (int s = 0; s < 4; s++) {
                v[s][0] = v[s][1] = 0x7fffffff;
                ii[s][0] = ii[s][1] = 0;
            }
        }
    };

    // ---- flush: merge lane-tops + dtop -> g_cand[(mb*128+row)*15 + c*3 ..] ----
    auto flushMB = [&](int mb) {
        // slot index c = cta - first CTA touching mb
        int um = mb * NTILE;
        int i0 = (int)(((long long)um * NCTA_S) / TOTU);
        while ((int)(((long long)TOTU * (i0 + 1)) / NCTA_S) <= um) i0++;
        while ((int)(((long long)TOTU * i0) / NCTA_S) > um) i0--;
        const int c = cta - i0;              // 0..4
        // IMMA lanes deposit their top-2 into dtop slots 16..23
        if (wid < 4) {
#pragma unroll
            for (int s = 0; s < 4; s++) {
                int rloc = wm * 32 + (s >> 1) * 16 + (s & 1) * 8 + gr;
                Ent* er = (Ent*)(smem + DTOP_OFF + rloc * DTOP_STR);
#pragma unroll
                for (int j = 0; j < 2; j++)
                    er[16 + q * 2 + j] = Ent{v[s][j], ii[s][j]};
            }
        }
        __syncthreads();
        if (tid < 128) {
            const int row = tid;
            Ent* er = (Ent*)(smem + DTOP_OFF + row * DTOP_STR);
            int outb = (mb * 128 + row) * NREF + c * NKEEP;
            for (int pc = 0; pc < NKEEP; pc++) {
                int bv = 0x7fffffff, bi = 0x7fffffff, bs = 0;
                for (int s = 0; s < 24; s++) {
                    int ev = er[s].v, ei = er[s].i;
                    if (ev < bv || (ev == bv && ei < bi)) { bv = ev; bi = ei; bs = s; }
                }
                er[bs].v = 0x7fffffff;
                g_cand[outb + pc] = bi;
            }
        }
    };

    int cur_mb = u0 / NTILE;
    setupMB(cur_mb);
    loadB(u0 % NTILE, 0);
    cp_commit();

    for (int u = u0; u < u1; u++) {
        const int k = u - u0;
        if (u + 1 < u1) { loadB((u + 1) % NTILE, (k + 1) & 1); cp_commit(); cp_wait<1>(); }
        else            { cp_wait<0>(); }

        const int mb = u / NTILE, t = u % NTILE;
        if (mb != cur_mb) {
            __syncthreads();             // dp4a dtop writes + compute done
            flushMB(cur_mb);
            __syncthreads();             // flush reads done
            setupMB(mb);
            cur_mb = mb;
        }
        __syncthreads();                 // B stage + (A/dtop if reset) visible

        const int st = k & 1;
        const uint32_t bbase = sb + B_OFF + st * B_STAGE;
        const uint32_t cnb = sb + ICN_OFF + st * 512;

        if (wid < 4) {
            // ---------- IMMA: codes 0..87 ----------
#pragma unroll
            for (int nb = 0; nb < 11; nb++) {
                const int nloc = nb * 8;
                const uint32_t rowb = bbase + (uint32_t)(nloc + gr) * 128 + q * 4;
                int b[4][2];
#pragma unroll
                for (int ks = 0; ks < 4; ks++) {
                    b[ks][0] = lds32(rowb + ((uint32_t)((2 * ks)     ^ gr) << 4));
                    b[ks][1] = lds32(rowb + ((uint32_t)((2 * ks + 1) ^ gr) << 4));
                }
                const int2 icn = lds64(cnb + (uint32_t)(nloc + 2 * q) * 4);
                const int ng = t * 128 + nloc + 2 * q;
#pragma unroll
                for (int g2 = 0; g2 < 2; g2++) {
                    int d[4] = {0, 0, 0, 0};
#pragma unroll
                    for (int ks = 0; ks < 4; ks++)
                        mma_s8(d, a[g2][ks], b[ks][0], b[ks][1]);
                    const int slo = g2 * 2, shi = g2 * 2 + 1;
                    ins2(icn.x - d[0], ng,     v[slo], ii[slo]);
                    ins2(icn.y - d[1], ng + 1, v[slo], ii[slo]);
                    ins2(icn.x - d[2], ng,     v[shi], ii[shi]);
                    ins2(icn.y - d[3], ng + 1, v[shi], ii[shi]);
                }
            }
        } else {
            // ---------- DP4A: codes 88..127 (5 per dtx lane), rows {dty+16r} ----------
            int acc[8][5];
#pragma unroll
            for (int r = 0; r < 8; r++)
#pragma unroll
                for (int j = 0; j < 5; j++) acc[r][j] = 0;

            const uint32_t bj0 = bbase + (uint32_t)(88 + dtx) * 128;
            const uint32_t abase = sb + dty * A_STRIDE;

#pragma unroll 4
            for (int ip = 0; ip < 16; ip++) {
                const uint32_t boff = (((uint32_t)((ip >> 1) ^ dtx)) << 4)
                                    + ((uint32_t)(ip & 1) << 3);
                int2 b2[5];
#pragma unroll
                for (int j = 0; j < 5; j++) b2[j] = lds64(bj0 + (uint32_t)(j * 8) * 128 + boff);
#pragma unroll
                for (int r = 0; r < 8; r++) {
                    int2 a2 = lds64(abase + r * (16 * A_STRIDE) + ip * 8);
#pragma unroll
                    for (int j = 0; j < 5; j++) {
                        dp4a(acc[r][j], a2.x, b2[j].x);
                        dp4a(acc[r][j], a2.y, b2[j].y);
                    }
                }
            }

            int icnv[5];
#pragma unroll
            for (int j = 0; j < 5; j++)
                icnv[j] = lds32(cnb + (uint32_t)(88 + j * 8 + dtx) * 4);
#pragma unroll
            for (int r = 0; r < 8; r++) {
                const int row = dty + 16 * r;
                int bv = icnv[0] - acc[r][0];
                int bi = t * 128 + 88 + dtx;
#pragma unroll
                for (int j = 1; j < 5; j++) {
                    int s = icnv[j] - acc[r][j];
                    int n = t * 128 + 88 + j * 8 + dtx;
                    if (s < bv) { bv = s; bi = n; }
                }
                int4* slot = (int4*)(smem + DTOP_OFF + row * DTOP_STR + dtx * 16);
                int4 e = *slot;
                if (bv < e.z) {
                    if (bv < e.x) { e.z = e.x; e.w = e.y; e.x = bv; e.y = bi; }
                    else          { e.z = bv; e.w = bi; }
                    *slot = e;
                }
            }
        }
        __syncthreads();
    }

    flushMB(cur_mb);
}

// ---------------- exact fp32 refinement + fused gather / error ----------------
__global__ void refine_kernel(const float* __restrict__ X, float* __restrict__ out) {
    const int wid = threadIdx.x >> 5, lid = threadIdx.x & 31;
    const int m = blockIdx.x * 8 + wid;
    float4 xv = ((const float4*)X)[(size_t)m * 32 + lid];
    float bestv = CUDART_INF_F; int besti = 0x7fffffff;
#pragma unroll
    for (int c = 0; c < NREF; c++) {
        int j = g_cand[m * NREF + c];
        float4 cv = ((const float4*)g_ctf)[(size_t)j * 32 + lid];
        float p = xv.x * cv.x;
        p = fmaf(xv.y, cv.y, p);
        p = fmaf(xv.z, cv.z, p);
        p = fmaf(xv.w, cv.w, p);
#pragma unroll
        for (int off = 16; off > 0; off >>= 1)
            p += __shfl_xor_sync(0xFFFFFFFF, p, off);
        float s = fmaf(-2.f, p, g_cnorm[j]);
        if (s < bestv || (s == bestv && j < besti)) { bestv = s; besti = j; }
    }
    float4 cv = ((const float4*)g_ctf)[(size_t)besti * 32 + lid];
    ((float4*)out)[(size_t)m * 32 + lid] = cv;
    float dx = cv.x - xv.x, dy = cv.y - xv.y, dz = cv.z - xv.z, dw = cv.w - xv.w;
    float e = dx * dx + dy * dy + dz * dz + dw * dw;
#pragma unroll
    for (int off = 16; off > 0; off >>= 1)
        e += __shfl_xor_sync(0xFFFFFFFF, e, off);
    if (lid == 0) g_partial[m] = e;
}

// ---------------- deterministic loss reduction ----------------
__global__ void loss_kernel(float* __restrict__ out, int out_size) {
    __shared__ float sbuf[1024];
    int t = threadIdx.x;
    float s = 0.f;
    for (int i = 0; i < NSAMP / 1024; i++) s += g_partial[t + i * 1024];
    sbuf[t] = s;
    __syncthreads();
    for (int k = 512; k > 0; k >>= 1) {
        if (t < k) sbuf[t] += sbuf[t + k];
        __syncthreads();
    }
    if (t == 0)
        out[out_size - 1] = sbuf[0] * (1.25f / (float)((size_t)NSAMP * EMBED_D));
}

// ---------------- launch ----------------
extern "C" void kernel_launch(void* const* d_in, const int* in_sizes, int n_in,
                              void* d_out, int out_size) {
    const float* X  = (const float*)d_in[0];
    const float* CM = (const float*)d_in[1];
    if (n_in >= 2 && in_sizes[0] == EMBED_D * N_EMBED &&
        in_sizes[1] == NSAMP * EMBED_D) {
        const float* t = X; X = CM; CM = t;
    }
    float* out = (float*)d_out;

    cudaFuncSetAttribute(screen_kernel,
                         cudaFuncAttributeMaxDynamicSharedMemorySize, SMEM_SZ);

    prep_kernel<<<PREP_CB + PREP_XB + PREP_ZB, 128>>>(X, CM);
    screen_kernel<<<NCTA_S, 256, SMEM_SZ>>>();
    refine_kernel<<<NSAMP / 8, 256>>>(X, out);
    loss_kernel<<<1, 1024>>>(out, out_size);
}